// round 2
// baseline (speedup 1.0000x reference)
#include <cuda_runtime.h>
#include <math.h>

// Problem constants
#define B_    16
#define N_    4096
#define C_    256
#define HH_   64
#define WW_   64
#define HEADS_ 8
#define D_    32
#define HID_  1024
#define ROWS_ 65536          // B_*N_

// ---------------- scratch (device globals; no allocation allowed) ----------
__device__ float g_xn  [ROWS_ * C_];        // norm1(x)
__device__ float g_b1  [ROWS_ * C_];        // x_ -> xa -> x2
__device__ float g_b2  [ROWS_ * C_];        // attn -> ln2norm -> x3
__device__ float g_qkv [ROWS_ * 3 * C_];    // qkv
__device__ float g_h1  [ROWS_ * HID_];      // fc1 out
__device__ float g_h2  [ROWS_ * HID_];      // dwconv+gelu out
__device__ float g_pm  [B_ * 16 * C_];      // q-softmax partial max
__device__ float g_ps  [B_ * 16 * C_];      // q-softmax partial sum
__device__ float g_cmax[B_ * C_];
__device__ float g_cinv[B_ * C_];
__device__ float g_ctxp[16 * B_ * HEADS_ * D_ * D_]; // ctx partials (16 chunks)
__device__ float g_ctx [B_ * HEADS_ * D_ * D_];
__device__ float g_cps [B_ * 32 * C_];
__device__ float g_cpm [B_ * 32 * C_];
__device__ float g_avg [B_ * C_];
__device__ float g_mx  [B_ * C_];
__device__ float g_ca  [B_ * C_];
__device__ float g_sm  [ROWS_];
__device__ float g_sx  [ROWS_];
__device__ float g_sa  [ROWS_];

__device__ __forceinline__ float geluf(float x) {
    return 0.5f * x * (1.0f + erff(x * 0.70710678118654752440f));
}
__device__ __forceinline__ float sigmf(float x) {
    return 1.0f / (1.0f + __expf(-x));
}

// ---------------- LayerNorm (256 wide), one warp per row --------------------
__global__ void ln256(const float* __restrict__ in, float* __restrict__ out,
                      const float* __restrict__ g, const float* __restrict__ bt)
{
    int w = (blockIdx.x * blockDim.x + threadIdx.x) >> 5;
    int lane = threadIdx.x & 31;
    if (w >= ROWS_) return;
    const float* r = in + (size_t)w * C_;
    float4 a = *(const float4*)(r + lane * 4);
    float4 b = *(const float4*)(r + 128 + lane * 4);
    float s = a.x + a.y + a.z + a.w + b.x + b.y + b.z + b.w;
    float q = a.x*a.x + a.y*a.y + a.z*a.z + a.w*a.w
            + b.x*b.x + b.y*b.y + b.z*b.z + b.w*b.w;
    #pragma unroll
    for (int o = 16; o; o >>= 1) {
        s += __shfl_xor_sync(0xffffffffu, s, o);
        q += __shfl_xor_sync(0xffffffffu, q, o);
    }
    float mean = s * (1.0f / C_);
    float inv = rsqrtf(q * (1.0f / C_) - mean * mean + 1e-5f);
    float4 g0 = *(const float4*)(g + lane * 4);
    float4 g1 = *(const float4*)(g + 128 + lane * 4);
    float4 b0 = *(const float4*)(bt + lane * 4);
    float4 b1 = *(const float4*)(bt + 128 + lane * 4);
    float4 o0, o1;
    o0.x = (a.x - mean) * inv * g0.x + b0.x;
    o0.y = (a.y - mean) * inv * g0.y + b0.y;
    o0.z = (a.z - mean) * inv * g0.z + b0.z;
    o0.w = (a.w - mean) * inv * g0.w + b0.w;
    o1.x = (b.x - mean) * inv * g1.x + b1.x;
    o1.y = (b.y - mean) * inv * g1.y + b1.y;
    o1.z = (b.z - mean) * inv * g1.z + b1.z;
    o1.w = (b.w - mean) * inv * g1.w + b1.w;
    float* po = out + (size_t)w * C_;
    *(float4*)(po + lane * 4) = o0;
    *(float4*)(po + 128 + lane * 4) = o1;
}

// xa = xn + gelu(LN(buf))   (in-place over buf)
__global__ void ln_gelu_add(float* __restrict__ buf, const float* __restrict__ xn,
                            const float* __restrict__ g, const float* __restrict__ bt)
{
    int w = (blockIdx.x * blockDim.x + threadIdx.x) >> 5;
    int lane = threadIdx.x & 31;
    if (w >= ROWS_) return;
    float* r = buf + (size_t)w * C_;
    const float* xr = xn + (size_t)w * C_;
    float4 a = *(const float4*)(r + lane * 4);
    float4 b = *(const float4*)(r + 128 + lane * 4);
    float s = a.x + a.y + a.z + a.w + b.x + b.y + b.z + b.w;
    float q = a.x*a.x + a.y*a.y + a.z*a.z + a.w*a.w
            + b.x*b.x + b.y*b.y + b.z*b.z + b.w*b.w;
    #pragma unroll
    for (int o = 16; o; o >>= 1) {
        s += __shfl_xor_sync(0xffffffffu, s, o);
        q += __shfl_xor_sync(0xffffffffu, q, o);
    }
    float mean = s * (1.0f / C_);
    float inv = rsqrtf(q * (1.0f / C_) - mean * mean + 1e-5f);
    float4 g0 = *(const float4*)(g + lane * 4);
    float4 g1 = *(const float4*)(g + 128 + lane * 4);
    float4 b0 = *(const float4*)(bt + lane * 4);
    float4 b1 = *(const float4*)(bt + 128 + lane * 4);
    float4 x0 = *(const float4*)(xr + lane * 4);
    float4 x1 = *(const float4*)(xr + 128 + lane * 4);
    float4 o0, o1;
    o0.x = x0.x + geluf((a.x - mean) * inv * g0.x + b0.x);
    o0.y = x0.y + geluf((a.y - mean) * inv * g0.y + b0.y);
    o0.z = x0.z + geluf((a.z - mean) * inv * g0.z + b0.z);
    o0.w = x0.w + geluf((a.w - mean) * inv * g0.w + b0.w);
    o1.x = x1.x + geluf((b.x - mean) * inv * g1.x + b1.x);
    o1.y = x1.y + geluf((b.y - mean) * inv * g1.y + b1.y);
    o1.z = x1.z + geluf((b.z - mean) * inv * g1.z + b1.z);
    o1.w = x1.w + geluf((b.w - mean) * inv * g1.w + b1.w);
    *(float4*)(r + lane * 4) = o0;
    *(float4*)(r + 128 + lane * 4) = o1;
}

// ---------------- depthwise 3x3 "SAME" conv on [B,N,CH] layout --------------
template <int CH, bool GELU>
__global__ void dwconv3(const float* __restrict__ in, float* __restrict__ out,
                        const float* __restrict__ w, const float* __restrict__ bias)
{
    int idx = blockIdx.x * blockDim.x + threadIdx.x;
    const int C4 = CH / 4;
    if (idx >= B_ * N_ * C4) return;
    int c4 = idx % C4;
    int n  = (idx / C4) % N_;
    int b  = idx / (C4 * N_);
    int h = n >> 6, wp = n & 63;
    int c0 = c4 * 4;
    float wr[4][9];
    #pragma unroll
    for (int i = 0; i < 4; i++)
        #pragma unroll
        for (int k = 0; k < 9; k++)
            wr[i][k] = w[(c0 + i) * 9 + k];
    float4 acc;
    acc.x = bias[c0]; acc.y = bias[c0 + 1]; acc.z = bias[c0 + 2]; acc.w = bias[c0 + 3];
    #pragma unroll
    for (int dy = -1; dy <= 1; dy++) {
        int hh = h + dy;
        if ((unsigned)hh >= 64u) continue;
        #pragma unroll
        for (int dx = -1; dx <= 1; dx++) {
            int ww = wp + dx;
            if ((unsigned)ww >= 64u) continue;
            int k = (dy + 1) * 3 + (dx + 1);
            float4 v = *(const float4*)(in + ((size_t)(b * N_ + hh * 64 + ww)) * CH + c0);
            acc.x += v.x * wr[0][k];
            acc.y += v.y * wr[1][k];
            acc.z += v.z * wr[2][k];
            acc.w += v.w * wr[3][k];
        }
    }
    if (GELU) {
        acc.x = geluf(acc.x); acc.y = geluf(acc.y);
        acc.z = geluf(acc.z); acc.w = geluf(acc.w);
    }
    *(float4*)(out + ((size_t)(b * N_ + n)) * CH + c0) = acc;
}

// ---------------- SGEMM: C[M,N] = A[M,K] @ W[N,K]^T (+bias,+res1,+res2) -----
#define GBM 128
#define GBN 128
#define GBK 8
__global__ __launch_bounds__(256)
void sgemm(const float* __restrict__ A, const float* __restrict__ W,
           float* __restrict__ Cout, int M, int N, int K,
           const float* __restrict__ bias,
           const float* __restrict__ r1, const float* __restrict__ r2)
{
    __shared__ float As[GBK][GBM];
    __shared__ float Bs[GBK][GBN];
    int tid = threadIdx.x;
    int bm = blockIdx.y * GBM;
    int bn = blockIdx.x * GBN;
    int lr = tid >> 1;
    int lk = (tid & 1) * 4;
    int tm0 = (tid >> 4) * 8;
    int tn0 = (tid & 15) * 8;
    float acc[8][8] = {};
    const float* Ap = A + (size_t)(bm + lr) * K + lk;
    const float* Wp = W + (size_t)(bn + lr) * K + lk;
    for (int k0 = 0; k0 < K; k0 += GBK) {
        float4 a4 = *(const float4*)(Ap + k0);
        float4 b4 = *(const float4*)(Wp + k0);
        As[lk + 0][lr] = a4.x; As[lk + 1][lr] = a4.y;
        As[lk + 2][lr] = a4.z; As[lk + 3][lr] = a4.w;
        Bs[lk + 0][lr] = b4.x; Bs[lk + 1][lr] = b4.y;
        Bs[lk + 2][lr] = b4.z; Bs[lk + 3][lr] = b4.w;
        __syncthreads();
        #pragma unroll
        for (int kk = 0; kk < GBK; kk++) {
            float ra[8], rb[8];
            #pragma unroll
            for (int i = 0; i < 8; i++) ra[i] = As[kk][tm0 + i];
            #pragma unroll
            for (int j = 0; j < 8; j++) rb[j] = Bs[kk][tn0 + j];
            #pragma unroll
            for (int i = 0; i < 8; i++)
                #pragma unroll
                for (int j = 0; j < 8; j++)
                    acc[i][j] += ra[i] * rb[j];
        }
        __syncthreads();
    }
    #pragma unroll
    for (int i = 0; i < 8; i++) {
        size_t row = bm + tm0 + i;
        #pragma unroll
        for (int j = 0; j < 8; j++) {
            int col = bn + tn0 + j;
            float v = acc[i][j];
            if (bias) v += bias[col];
            if (r1) v += r1[row * N + col];
            if (r2) v += r2[row * N + col];
            Cout[row * N + col] = v;
        }
    }
}

// ---------------- q softmax over tokens: per-(b,c) online partials ----------
__global__ void qsoft_part(const float* __restrict__ qkv)
{
    int b = blockIdx.x, ch = blockIdx.y, c = threadIdx.x;
    const float* p = qkv + ((size_t)(b * N_ + ch * 256)) * (3 * C_) + c;
    float m = -1e30f, s = 0.0f;
    for (int i = 0; i < 256; i++) {
        float v = p[(size_t)i * (3 * C_)];
        float nm = fmaxf(m, v);
        s = s * __expf(m - nm) + __expf(v - nm);
        m = nm;
    }
    g_pm[(b * 16 + ch) * C_ + c] = m;
    g_ps[(b * 16 + ch) * C_ + c] = s;
}

__global__ void qsoft_comb()
{
    int idx = blockIdx.x * blockDim.x + threadIdx.x;  // B_*C_
    if (idx >= B_ * C_) return;
    int b = idx >> 8, c = idx & 255;
    float M = -1e30f;
    for (int ch = 0; ch < 16; ch++) M = fmaxf(M, g_pm[(b * 16 + ch) * C_ + c]);
    float S = 0.0f;
    for (int ch = 0; ch < 16; ch++)
        S += g_ps[(b * 16 + ch) * C_ + c] * __expf(g_pm[(b * 16 + ch) * C_ + c] - M);
    g_cmax[idx] = M;
    g_cinv[idx] = 1.0f / S;
}

// ---------------- ctx = softmax_d(k)^T @ v  per (b,head), chunked -----------
__global__ __launch_bounds__(256) void ctx_kernel(const float* __restrict__ qkv)
{
    int chunk = blockIdx.x;   // 16 chunks of 256 tokens
    int head  = blockIdx.y;   // 8
    int b     = blockIdx.z;   // 16
    __shared__ float ks[32][33];
    __shared__ float vs[32][33];
    int tid = threadIdx.x, lane = tid & 31, wp = tid >> 5;
    float acc[4] = {0.f, 0.f, 0.f, 0.f};
    for (int it = 0; it < 8; it++) {
        int nb = chunk * 256 + it * 32;
        #pragma unroll
        for (int j = 0; j < 8; j++) {
            int id = tid + 256 * j;
            int r = id >> 6, inner = id & 63;
            const float* src = qkv + ((size_t)(b * N_ + nb + r)) * (3 * C_) + C_ + head * D_;
            if (inner < 32) ks[r][inner] = src[inner];
            else            vs[r][inner - 32] = src[C_ + inner - 32];
        }
        __syncthreads();
        // row softmax over d=32 for 4 rows per warp
        #pragma unroll
        for (int rr = 0; rr < 4; rr++) {
            int r = wp * 4 + rr;
            float v = ks[r][lane];
            float mx = v;
            #pragma unroll
            for (int o = 16; o; o >>= 1) mx = fmaxf(mx, __shfl_xor_sync(0xffffffffu, mx, o));
            float e = __expf(v - mx);
            float su = e;
            #pragma unroll
            for (int o = 16; o; o >>= 1) su += __shfl_xor_sync(0xffffffffu, su, o);
            ks[r][lane] = e / su;
        }
        __syncthreads();
        #pragma unroll
        for (int r = 0; r < 32; r++) {
            float vv = vs[r][lane];
            #pragma unroll
            for (int i = 0; i < 4; i++) acc[i] += ks[r][wp + 8 * i] * vv;
        }
        __syncthreads();
    }
    #pragma unroll
    for (int i = 0; i < 4; i++) {
        int e = wp + 8 * i;
        g_ctxp[(size_t)chunk * (B_ * HEADS_ * D_ * D_) +
               ((b * HEADS_ + head) * D_ + e) * D_ + lane] = acc[i];
    }
}

__global__ void ctx_comb()
{
    int idx = blockIdx.x * blockDim.x + threadIdx.x;  // B_*HEADS_*D_*D_
    if (idx >= B_ * HEADS_ * D_ * D_) return;
    float s = 0.0f;
    for (int ch = 0; ch < 16; ch++) s += g_ctxp[(size_t)ch * (B_ * HEADS_ * D_ * D_) + idx];
    g_ctx[idx] = s;
}

// ---------------- attn = softmax_N(q) @ ctx ---------------------------------
__global__ __launch_bounds__(256) void attn_kernel(const float* __restrict__ qkv,
                                                   float* __restrict__ out)
{
    __shared__ float ctxs[HEADS_ * D_ * D_];   // 8192 floats
    __shared__ float qs[C_], cm[C_], ci[C_];
    int b = blockIdx.y, ch = blockIdx.x;       // 16 x 64 (chunks of 64 rows)
    int tid = threadIdx.x;
    for (int j = tid; j < HEADS_ * D_ * D_; j += 256)
        ctxs[j] = g_ctx[b * HEADS_ * D_ * D_ + j];
    cm[tid] = g_cmax[b * C_ + tid];
    ci[tid] = g_cinv[b * C_ + tid];
    __syncthreads();
    int hh = tid >> 5, f = tid & 31;
    const float* ctxrow = ctxs + hh * (D_ * D_) + f;
    for (int j = 0; j < 64; j++) {
        size_t n = (size_t)b * N_ + ch * 64 + j;
        float qraw = qkv[n * (3 * C_) + tid];
        qs[tid] = __expf(qraw - cm[tid]) * ci[tid];
        __syncthreads();
        float s = 0.0f;
        #pragma unroll
        for (int e = 0; e < 32; e++) s += qs[hh * 32 + e] * ctxrow[e * 32];
        out[n * C_ + tid] = s;
        __syncthreads();
    }
}

// ---------------- CSDA ------------------------------------------------------
__global__ void cpool_part(const float* __restrict__ x3)
{
    int b = blockIdx.x, ch = blockIdx.y, c = threadIdx.x;
    const float* p = x3 + ((size_t)(b * N_ + ch * 128)) * C_ + c;
    float s = 0.0f, m = -1e30f;
    for (int i = 0; i < 128; i++) {
        float v = p[(size_t)i * C_];
        s += v; m = fmaxf(m, v);
    }
    g_cps[(b * 32 + ch) * C_ + c] = s;
    g_cpm[(b * 32 + ch) * C_ + c] = m;
}

__global__ void cpool_comb()
{
    int idx = blockIdx.x * blockDim.x + threadIdx.x;  // B_*C_
    if (idx >= B_ * C_) return;
    int b = idx >> 8, c = idx & 255;
    float s = 0.0f, m = -1e30f;
    for (int ch = 0; ch < 32; ch++) {
        s += g_cps[(b * 32 + ch) * C_ + c];
        m = fmaxf(m, g_cpm[(b * 32 + ch) * C_ + c]);
    }
    g_avg[idx] = s * (1.0f / N_);
    g_mx[idx] = m;
}

__global__ void ca_mlp(const float* __restrict__ w1, const float* __restrict__ w2)
{
    int b = blockIdx.x, t = threadIdx.x;
    __shared__ float hsum[16];
    if (t < 16) {
        float sa = 0.0f, sm = 0.0f;
        for (int c = 0; c < C_; c++) {
            float w = w1[t * C_ + c];
            sa += g_avg[b * C_ + c] * w;
            sm += g_mx[b * C_ + c] * w;
        }
        hsum[t] = fmaxf(sa, 0.0f) + fmaxf(sm, 0.0f);
    }
    __syncthreads();
    float acc = 0.0f;
    #pragma unroll
    for (int j = 0; j < 16; j++) acc += w2[t * 16 + j] * hsum[j];
    g_ca[b * C_ + t] = sigmf(acc);
}

__global__ void spool(const float* __restrict__ x3)
{
    int w = (blockIdx.x * blockDim.x + threadIdx.x) >> 5;
    int lane = threadIdx.x & 31;
    if (w >= ROWS_) return;
    int b = w >> 12;
    const float* r = x3 + (size_t)w * C_;
    const float* ca = g_ca + b * C_;
    float4 a = *(const float4*)(r + lane * 4);
    float4 c0 = *(const float4*)(ca + lane * 4);
    float4 bvals = *(const float4*)(r + 128 + lane * 4);
    float4 c1 = *(const float4*)(ca + 128 + lane * 4);
    float v0 = a.x * c0.x, v1 = a.y * c0.y, v2 = a.z * c0.z, v3 = a.w * c0.w;
    float v4 = bvals.x * c1.x, v5 = bvals.y * c1.y, v6 = bvals.z * c1.z, v7 = bvals.w * c1.w;
    float s = v0 + v1 + v2 + v3 + v4 + v5 + v6 + v7;
    float m = fmaxf(fmaxf(fmaxf(v0, v1), fmaxf(v2, v3)), fmaxf(fmaxf(v4, v5), fmaxf(v6, v7)));
    #pragma unroll
    for (int o = 16; o; o >>= 1) {
        s += __shfl_xor_sync(0xffffffffu, s, o);
        m = fmaxf(m, __shfl_xor_sync(0xffffffffu, m, o));
    }
    if (lane == 0) {
        g_sm[w] = s * (1.0f / C_);
        g_sx[w] = m;
    }
}

__global__ void conv7(const float* __restrict__ spw, const float* __restrict__ spb)
{
    int idx = blockIdx.x * blockDim.x + threadIdx.x;   // ROWS_
    if (idx >= ROWS_) return;
    int b = idx >> 12, n = idx & 4095;
    int h = n >> 6, w = n & 63;
    float acc = spb[0];
    #pragma unroll
    for (int ch = 0; ch < 2; ch++) {
        const float* src = ch ? g_sx : g_sm;
        const float* wp = spw + ch * 49;
        for (int ky = 0; ky < 7; ky++) {
            int y = h + ky - 3;
            if ((unsigned)y >= 64u) continue;
            for (int kx = 0; kx < 7; kx++) {
                int x = w + kx - 3;
                if ((unsigned)x >= 64u) continue;
                acc += src[(b << 12) + (y << 6) + x] * wp[ky * 7 + kx];
            }
        }
    }
    g_sa[idx] = sigmf(acc);
}

__global__ void final_scale(const float* __restrict__ x3, float* __restrict__ out)
{
    int idx = blockIdx.x * blockDim.x + threadIdx.x;   // ROWS_*64
    if (idx >= ROWS_ * 64) return;
    int c4 = idx & 63;
    int row = idx >> 6;
    int b = row >> 12;
    float4 v = *(const float4*)(x3 + (size_t)row * C_ + c4 * 4);
    float4 ca = *(const float4*)(g_ca + b * C_ + c4 * 4);
    float sa = g_sa[row];
    v.x *= ca.x * sa; v.y *= ca.y * sa; v.z *= ca.z * sa; v.w *= ca.w * sa;
    *(float4*)(out + (size_t)row * C_ + c4 * 4) = v;
}

// ---------------------------------------------------------------------------
extern "C" void kernel_launch(void* const* d_in, const int* in_sizes, int n_in,
                              void* d_out, int out_size)
{
    // Input mapping: optional scalar H, W at indices 1,2
    int p = (n_in >= 24 && in_sizes[1] == 1 && in_sizes[2] == 1) ? 3 : 1;
    const float* x      = (const float*)d_in[0];
    const float* n1_g   = (const float*)d_in[p + 0];
    const float* n1_b   = (const float*)d_in[p + 1];
    const float* sr_w   = (const float*)d_in[p + 2];
    const float* sr_b   = (const float*)d_in[p + 3];
    const float* an_g   = (const float*)d_in[p + 4];
    const float* an_b   = (const float*)d_in[p + 5];
    const float* qkv_w  = (const float*)d_in[p + 6];
    const float* proj_w = (const float*)d_in[p + 7];
    const float* proj_b = (const float*)d_in[p + 8];
    const float* n2_g   = (const float*)d_in[p + 9];
    const float* n2_b   = (const float*)d_in[p + 10];
    const float* fc1_w  = (const float*)d_in[p + 11];
    const float* fc1_b  = (const float*)d_in[p + 12];
    const float* dw_w   = (const float*)d_in[p + 13];
    const float* dw_b   = (const float*)d_in[p + 14];
    const float* fc2_w  = (const float*)d_in[p + 15];
    const float* fc2_b  = (const float*)d_in[p + 16];
    const float* ca_w1  = (const float*)d_in[p + 17];
    const float* ca_w2  = (const float*)d_in[p + 18];
    const float* sp_w   = (const float*)d_in[p + 19];
    const float* sp_b   = (const float*)d_in[p + 20];
    float* out = (float*)d_out;

    float *pxn, *pb1, *pb2, *pqkv, *ph1, *ph2;
    cudaGetSymbolAddress((void**)&pxn,  g_xn);
    cudaGetSymbolAddress((void**)&pb1,  g_b1);
    cudaGetSymbolAddress((void**)&pb2,  g_b2);
    cudaGetSymbolAddress((void**)&pqkv, g_qkv);
    cudaGetSymbolAddress((void**)&ph1,  g_h1);
    cudaGetSymbolAddress((void**)&ph2,  g_h2);

    const int TPB = 256;

    // 1. xn = LN1(x)
    ln256<<<ROWS_ * 32 / TPB, TPB>>>(x, pxn, n1_g, n1_b);
    // 2. x_ = dwconv3(xn)          -> b1
    dwconv3<C_, false><<<(B_ * N_ * (C_ / 4) + TPB - 1) / TPB, TPB>>>(pxn, pb1, sr_w, sr_b);
    // 3. xa = xn + gelu(LN_act(x_)) (in-place b1)
    ln_gelu_add<<<ROWS_ * 32 / TPB, TPB>>>(pb1, pxn, an_g, an_b);
    // 4. qkv = xa @ qkv_w^T
    {
        dim3 g(3 * C_ / GBN, ROWS_ / GBM);
        sgemm<<<g, TPB>>>(pb1, qkv_w, pqkv, ROWS_, 3 * C_, C_, nullptr, nullptr, nullptr);
    }
    // 5. q column-softmax stats
    {
        dim3 g(B_, 16);
        qsoft_part<<<g, TPB>>>(pqkv);
        qsoft_comb<<<(B_ * C_ + TPB - 1) / TPB, TPB>>>();
    }
    // 6. ctx = softmax_d(k)^T v
    {
        dim3 g(16, HEADS_, B_);
        ctx_kernel<<<g, TPB>>>(pqkv);
        ctx_comb<<<(B_ * HEADS_ * D_ * D_ + TPB - 1) / TPB, TPB>>>();
    }
    // 7. attn = softmax_N(q) @ ctx -> b2
    {
        dim3 g(64, B_);
        attn_kernel<<<g, TPB>>>(pqkv, pb2);
    }
    // 8. x2 = x + attn @ proj_w^T + proj_b + xn  -> b1
    {
        dim3 g(C_ / GBN, ROWS_ / GBM);
        sgemm<<<g, TPB>>>(pb2, proj_w, pb1, ROWS_, C_, C_, proj_b, x, pxn);
    }
    // 9. ln2(x2) -> b2
    ln256<<<ROWS_ * 32 / TPB, TPB>>>(pb1, pb2, n2_g, n2_b);
    // 10. fc1 -> h1
    {
        dim3 g(HID_ / GBN, ROWS_ / GBM);
        sgemm<<<g, TPB>>>(pb2, fc1_w, ph1, ROWS_, HID_, C_, fc1_b, nullptr, nullptr);
    }
    // 11. dwconv + gelu -> h2
    dwconv3<HID_, true><<<(B_ * N_ * (HID_ / 4) + TPB - 1) / TPB, TPB>>>(ph1, ph2, dw_w, dw_b);
    // 12. x3 = x2 + gelu_dw @ fc2_w^T + fc2_b  -> b2
    {
        dim3 g(C_ / GBN, ROWS_ / GBM);
        sgemm<<<g, TPB>>>(ph2, fc2_w, pb2, ROWS_, C_, HID_, fc2_b, pb1, nullptr);
    }
    // 13. channel pools
    {
        dim3 g(B_, 32);
        cpool_part<<<g, TPB>>>(pb2);
        cpool_comb<<<(B_ * C_ + TPB - 1) / TPB, TPB>>>();
    }
    // 14. channel attention MLP
    ca_mlp<<<B_, TPB>>>(ca_w1, ca_w2);
    // 15. spatial pools of x3*ca
    spool<<<ROWS_ * 32 / TPB, TPB>>>(pb2);
    // 16. 7x7 spatial conv -> sa
    conv7<<<(ROWS_ + TPB - 1) / TPB, TPB>>>(sp_w, sp_b);
    // 17. out = x3 * ca * sa
    final_scale<<<(ROWS_ * 64 + TPB - 1) / TPB, TPB>>>(pb2, out);
}

// round 3
// speedup vs baseline: 1.4689x; 1.4689x over previous
#include <cuda_runtime.h>
#include <math.h>
#include <stdint.h>

// Problem constants
#define B_    16
#define N_    4096
#define C_    256
#define HH_   64
#define WW_   64
#define HEADS_ 8
#define D_    32
#define HID_  1024
#define ROWS_ 65536          // B_*N_

// ---------------- scratch (device globals; no allocation allowed) ----------
__device__ float g_xn  [ROWS_ * C_];        // norm1(x)
__device__ float g_b1  [ROWS_ * C_];        // x_ -> xa -> x2
__device__ float g_b2  [ROWS_ * C_];        // attn -> ln2norm -> x3
__device__ float g_qkv [ROWS_ * 3 * C_];    // qkv
__device__ float g_h1  [ROWS_ * HID_];      // fc1 out
__device__ float g_h2  [ROWS_ * HID_];      // dwconv+gelu out
__device__ float g_pm  [B_ * 16 * C_];      // q-softmax partial max
__device__ float g_ps  [B_ * 16 * C_];      // q-softmax partial sum
__device__ float g_cmax[B_ * C_];
__device__ float g_cinv[B_ * C_];
__device__ float g_ctxp[16 * B_ * HEADS_ * D_ * D_]; // ctx partials (16 chunks)
__device__ float g_ctx [B_ * HEADS_ * D_ * D_];
__device__ float g_cps [B_ * 32 * C_];
__device__ float g_cpm [B_ * 32 * C_];
__device__ float g_avg [B_ * C_];
__device__ float g_mx  [B_ * C_];
__device__ float g_ca  [B_ * C_];
__device__ float g_sm  [ROWS_];
__device__ float g_sx  [ROWS_];
__device__ float g_sa  [ROWS_];

__device__ __forceinline__ float geluf(float x) {
    return 0.5f * x * (1.0f + erff(x * 0.70710678118654752440f));
}
__device__ __forceinline__ float sigmf(float x) {
    return 1.0f / (1.0f + __expf(-x));
}

// ---------------- LayerNorm (256 wide), one warp per row --------------------
__global__ void ln256(const float* __restrict__ in, float* __restrict__ out,
                      const float* __restrict__ g, const float* __restrict__ bt)
{
    int w = (blockIdx.x * blockDim.x + threadIdx.x) >> 5;
    int lane = threadIdx.x & 31;
    if (w >= ROWS_) return;
    const float* r = in + (size_t)w * C_;
    float4 a = *(const float4*)(r + lane * 4);
    float4 b = *(const float4*)(r + 128 + lane * 4);
    float s = a.x + a.y + a.z + a.w + b.x + b.y + b.z + b.w;
    float q = a.x*a.x + a.y*a.y + a.z*a.z + a.w*a.w
            + b.x*b.x + b.y*b.y + b.z*b.z + b.w*b.w;
    #pragma unroll
    for (int o = 16; o; o >>= 1) {
        s += __shfl_xor_sync(0xffffffffu, s, o);
        q += __shfl_xor_sync(0xffffffffu, q, o);
    }
    float mean = s * (1.0f / C_);
    float inv = rsqrtf(q * (1.0f / C_) - mean * mean + 1e-5f);
    float4 g0 = *(const float4*)(g + lane * 4);
    float4 g1 = *(const float4*)(g + 128 + lane * 4);
    float4 b0 = *(const float4*)(bt + lane * 4);
    float4 b1 = *(const float4*)(bt + 128 + lane * 4);
    float4 o0, o1;
    o0.x = (a.x - mean) * inv * g0.x + b0.x;
    o0.y = (a.y - mean) * inv * g0.y + b0.y;
    o0.z = (a.z - mean) * inv * g0.z + b0.z;
    o0.w = (a.w - mean) * inv * g0.w + b0.w;
    o1.x = (b.x - mean) * inv * g1.x + b1.x;
    o1.y = (b.y - mean) * inv * g1.y + b1.y;
    o1.z = (b.z - mean) * inv * g1.z + b1.z;
    o1.w = (b.w - mean) * inv * g1.w + b1.w;
    float* po = out + (size_t)w * C_;
    *(float4*)(po + lane * 4) = o0;
    *(float4*)(po + 128 + lane * 4) = o1;
}

// xa = xn + gelu(LN(buf))   (in-place over buf)
__global__ void ln_gelu_add(float* __restrict__ buf, const float* __restrict__ xn,
                            const float* __restrict__ g, const float* __restrict__ bt)
{
    int w = (blockIdx.x * blockDim.x + threadIdx.x) >> 5;
    int lane = threadIdx.x & 31;
    if (w >= ROWS_) return;
    float* r = buf + (size_t)w * C_;
    const float* xr = xn + (size_t)w * C_;
    float4 a = *(const float4*)(r + lane * 4);
    float4 b = *(const float4*)(r + 128 + lane * 4);
    float s = a.x + a.y + a.z + a.w + b.x + b.y + b.z + b.w;
    float q = a.x*a.x + a.y*a.y + a.z*a.z + a.w*a.w
            + b.x*b.x + b.y*b.y + b.z*b.z + b.w*b.w;
    #pragma unroll
    for (int o = 16; o; o >>= 1) {
        s += __shfl_xor_sync(0xffffffffu, s, o);
        q += __shfl_xor_sync(0xffffffffu, q, o);
    }
    float mean = s * (1.0f / C_);
    float inv = rsqrtf(q * (1.0f / C_) - mean * mean + 1e-5f);
    float4 g0 = *(const float4*)(g + lane * 4);
    float4 g1 = *(const float4*)(g + 128 + lane * 4);
    float4 b0 = *(const float4*)(bt + lane * 4);
    float4 b1 = *(const float4*)(bt + 128 + lane * 4);
    float4 x0 = *(const float4*)(xr + lane * 4);
    float4 x1 = *(const float4*)(xr + 128 + lane * 4);
    float4 o0, o1;
    o0.x = x0.x + geluf((a.x - mean) * inv * g0.x + b0.x);
    o0.y = x0.y + geluf((a.y - mean) * inv * g0.y + b0.y);
    o0.z = x0.z + geluf((a.z - mean) * inv * g0.z + b0.z);
    o0.w = x0.w + geluf((a.w - mean) * inv * g0.w + b0.w);
    o1.x = x1.x + geluf((b.x - mean) * inv * g1.x + b1.x);
    o1.y = x1.y + geluf((b.y - mean) * inv * g1.y + b1.y);
    o1.z = x1.z + geluf((b.z - mean) * inv * g1.z + b1.z);
    o1.w = x1.w + geluf((b.w - mean) * inv * g1.w + b1.w);
    *(float4*)(r + lane * 4) = o0;
    *(float4*)(r + 128 + lane * 4) = o1;
}

// ---------------- depthwise 3x3 "SAME" conv on [B,N,CH] layout --------------
template <int CH, bool GELU>
__global__ void dwconv3(const float* __restrict__ in, float* __restrict__ out,
                        const float* __restrict__ w, const float* __restrict__ bias)
{
    int idx = blockIdx.x * blockDim.x + threadIdx.x;
    const int C4 = CH / 4;
    if (idx >= B_ * N_ * C4) return;
    int c4 = idx % C4;
    int n  = (idx / C4) % N_;
    int b  = idx / (C4 * N_);
    int h = n >> 6, wp = n & 63;
    int c0 = c4 * 4;
    float wr[4][9];
    #pragma unroll
    for (int i = 0; i < 4; i++)
        #pragma unroll
        for (int k = 0; k < 9; k++)
            wr[i][k] = w[(c0 + i) * 9 + k];
    float4 acc;
    acc.x = bias[c0]; acc.y = bias[c0 + 1]; acc.z = bias[c0 + 2]; acc.w = bias[c0 + 3];
    #pragma unroll
    for (int dy = -1; dy <= 1; dy++) {
        int hh = h + dy;
        if ((unsigned)hh >= 64u) continue;
        #pragma unroll
        for (int dx = -1; dx <= 1; dx++) {
            int ww = wp + dx;
            if ((unsigned)ww >= 64u) continue;
            int k = (dy + 1) * 3 + (dx + 1);
            float4 v = *(const float4*)(in + ((size_t)(b * N_ + hh * 64 + ww)) * CH + c0);
            acc.x += v.x * wr[0][k];
            acc.y += v.y * wr[1][k];
            acc.z += v.z * wr[2][k];
            acc.w += v.w * wr[3][k];
        }
    }
    if (GELU) {
        acc.x = geluf(acc.x); acc.y = geluf(acc.y);
        acc.z = geluf(acc.z); acc.w = geluf(acc.w);
    }
    *(float4*)(out + ((size_t)(b * N_ + n)) * CH + c0) = acc;
}

// ---------------- TF32 tensor-core GEMM: C = A[M,K] @ W[N,K]^T --------------
// 128x128x32 tiles, 8 warps (2m x 4n), each warp 64x32 via m16n8k8 MMAs,
// 2-stage cp.async double buffering. M,N,K must be multiples of 128/128/32.
#define TSTRIDE 36            // 32 + 4 pad floats, keeps 16B align, no conflicts
#define TILEF   (128 * TSTRIDE)

__device__ __forceinline__ void cp16(uint32_t d, const void* s) {
    asm volatile("cp.async.cg.shared.global [%0], [%1], 16;" :: "r"(d), "l"(s));
}

__global__ __launch_bounds__(256, 2)
void gemm_tf32(const float* __restrict__ A, const float* __restrict__ W,
               float* __restrict__ Cout, int M, int N, int K,
               const float* __restrict__ bias,
               const float* __restrict__ r1, const float* __restrict__ r2)
{
    extern __shared__ float sh[];
    float* Ash = sh;                    // [2][128][TSTRIDE]
    float* Bsh = sh + 2 * TILEF;        // [2][128][TSTRIDE]

    int tid = threadIdx.x;
    int warp = tid >> 5, lane = tid & 31;
    int wm = warp >> 2, wn = warp & 3;  // 2 x 4 warp grid
    int bm = blockIdx.y * 128, bn = blockIdx.x * 128;
    int gr = lane >> 2, gc = lane & 3;

    float acc[4][4][4];
    #pragma unroll
    for (int i = 0; i < 4; i++)
        #pragma unroll
        for (int j = 0; j < 4; j++)
            #pragma unroll
            for (int q = 0; q < 4; q++) acc[i][j][q] = 0.0f;

    int KT = K >> 5;

    // -------- stage loader --------
    int ldr  = tid >> 3;            // 0..31 row step of 4 iterations -> 128 rows
    int ldc  = (tid & 7) * 4;       // 0..28 col float offset
    const float* Abase = A + (size_t)(bm + ldr) * K + ldc;
    const float* Wbase = W + (size_t)(bn + ldr) * K + ldc;
    uint32_t sAd = (uint32_t)__cvta_generic_to_shared(&Ash[ldr * TSTRIDE + ldc]);
    uint32_t sBd = (uint32_t)__cvta_generic_to_shared(&Bsh[ldr * TSTRIDE + ldc]);
    const uint32_t stageB = TILEF * 4;        // bytes per stage
    const uint32_t rowB   = 32 * TSTRIDE * 4; // 32 rows per load iter

    #define LOAD_STAGE(st, kb) do {                                            \
        uint32_t so = (st) * stageB;                                           \
        size_t go = (size_t)(kb) * 32;                                         \
        _Pragma("unroll")                                                      \
        for (int it = 0; it < 4; it++) {                                       \
            cp16(sAd + so + it * rowB, Abase + (size_t)(it * 32) * K + go);    \
            cp16(sBd + so + it * rowB, Wbase + (size_t)(it * 32) * K + go);    \
        }                                                                      \
        asm volatile("cp.async.commit_group;");                                \
    } while (0)

    LOAD_STAGE(0, 0);
    int st = 0;
    for (int kb = 0; kb < KT; kb++) {
        if (kb + 1 < KT) {
            LOAD_STAGE(st ^ 1, kb + 1);
            asm volatile("cp.async.wait_group 1;");
        } else {
            asm volatile("cp.async.wait_group 0;");
        }
        __syncthreads();

        const float* As = Ash + st * TILEF;
        const float* Bs = Bsh + st * TILEF;
        #pragma unroll
        for (int ks = 0; ks < 4; ks++) {
            int k0 = ks * 8;
            uint32_t a[4][4], b[4][2];
            #pragma unroll
            for (int i = 0; i < 4; i++) {
                const float* p = As + (wm * 64 + i * 16 + gr) * TSTRIDE + k0 + gc;
                a[i][0] = __float_as_uint(p[0]);
                a[i][1] = __float_as_uint(p[8 * TSTRIDE]);
                a[i][2] = __float_as_uint(p[4]);
                a[i][3] = __float_as_uint(p[8 * TSTRIDE + 4]);
            }
            #pragma unroll
            for (int j = 0; j < 4; j++) {
                const float* p = Bs + (wn * 32 + j * 8 + gr) * TSTRIDE + k0 + gc;
                b[j][0] = __float_as_uint(p[0]);
                b[j][1] = __float_as_uint(p[4]);
            }
            #pragma unroll
            for (int i = 0; i < 4; i++)
                #pragma unroll
                for (int j = 0; j < 4; j++)
                    asm volatile(
                        "mma.sync.aligned.m16n8k8.row.col.f32.tf32.tf32.f32 "
                        "{%0,%1,%2,%3}, {%4,%5,%6,%7}, {%8,%9}, {%0,%1,%2,%3};"
                        : "+f"(acc[i][j][0]), "+f"(acc[i][j][1]),
                          "+f"(acc[i][j][2]), "+f"(acc[i][j][3])
                        : "r"(a[i][0]), "r"(a[i][1]), "r"(a[i][2]), "r"(a[i][3]),
                          "r"(b[j][0]), "r"(b[j][1]));
        }
        __syncthreads();
        st ^= 1;
    }

    // -------- epilogue: bias + up to two residuals, float2 stores ----------
    #pragma unroll
    for (int i = 0; i < 4; i++) {
        int row0 = bm + wm * 64 + i * 16 + gr;
        #pragma unroll
        for (int j = 0; j < 4; j++) {
            int col = bn + wn * 32 + j * 8 + gc * 2;
            float bx = 0.f, by = 0.f;
            if (bias) { bx = bias[col]; by = bias[col + 1]; }
            size_t o0 = (size_t)row0 * N + col;
            size_t o1 = (size_t)(row0 + 8) * N + col;
            float v0 = acc[i][j][0] + bx, v1 = acc[i][j][1] + by;
            float v2 = acc[i][j][2] + bx, v3 = acc[i][j][3] + by;
            if (r1) {
                float2 p0 = *(const float2*)(r1 + o0);
                float2 p1 = *(const float2*)(r1 + o1);
                v0 += p0.x; v1 += p0.y; v2 += p1.x; v3 += p1.y;
            }
            if (r2) {
                float2 p0 = *(const float2*)(r2 + o0);
                float2 p1 = *(const float2*)(r2 + o1);
                v0 += p0.x; v1 += p0.y; v2 += p1.x; v3 += p1.y;
            }
            *(float2*)(Cout + o0) = make_float2(v0, v1);
            *(float2*)(Cout + o1) = make_float2(v2, v3);
        }
    }
}

// ---------------- q softmax over tokens: per-(b,c) online partials ----------
__global__ void qsoft_part(const float* __restrict__ qkv)
{
    int b = blockIdx.x, ch = blockIdx.y, c = threadIdx.x;
    const float* p = qkv + ((size_t)(b * N_ + ch * 256)) * (3 * C_) + c;
    float m = -1e30f, s = 0.0f;
    for (int i = 0; i < 256; i++) {
        float v = p[(size_t)i * (3 * C_)];
        float nm = fmaxf(m, v);
        s = s * __expf(m - nm) + __expf(v - nm);
        m = nm;
    }
    g_pm[(b * 16 + ch) * C_ + c] = m;
    g_ps[(b * 16 + ch) * C_ + c] = s;
}

__global__ void qsoft_comb()
{
    int idx = blockIdx.x * blockDim.x + threadIdx.x;  // B_*C_
    if (idx >= B_ * C_) return;
    int b = idx >> 8, c = idx & 255;
    float M = -1e30f;
    for (int ch = 0; ch < 16; ch++) M = fmaxf(M, g_pm[(b * 16 + ch) * C_ + c]);
    float S = 0.0f;
    for (int ch = 0; ch < 16; ch++)
        S += g_ps[(b * 16 + ch) * C_ + c] * __expf(g_pm[(b * 16 + ch) * C_ + c] - M);
    g_cmax[idx] = M;
    g_cinv[idx] = 1.0f / S;
}

// ---------------- ctx = softmax_d(k)^T @ v  per (b,head), chunked -----------
__global__ __launch_bounds__(256) void ctx_kernel(const float* __restrict__ qkv)
{
    int chunk = blockIdx.x;   // 16 chunks of 256 tokens
    int head  = blockIdx.y;   // 8
    int b     = blockIdx.z;   // 16
    __shared__ float ks[32][33];
    __shared__ float vs[32][33];
    int tid = threadIdx.x, lane = tid & 31, wp = tid >> 5;
    float acc[4] = {0.f, 0.f, 0.f, 0.f};
    for (int it = 0; it < 8; it++) {
        int nb = chunk * 256 + it * 32;
        #pragma unroll
        for (int j = 0; j < 8; j++) {
            int id = tid + 256 * j;
            int r = id >> 6, inner = id & 63;
            const float* src = qkv + ((size_t)(b * N_ + nb + r)) * (3 * C_) + C_ + head * D_;
            if (inner < 32) ks[r][inner] = src[inner];
            else            vs[r][inner - 32] = src[C_ + inner - 32];
        }
        __syncthreads();
        #pragma unroll
        for (int rr = 0; rr < 4; rr++) {
            int r = wp * 4 + rr;
            float v = ks[r][lane];
            float mx = v;
            #pragma unroll
            for (int o = 16; o; o >>= 1) mx = fmaxf(mx, __shfl_xor_sync(0xffffffffu, mx, o));
            float e = __expf(v - mx);
            float su = e;
            #pragma unroll
            for (int o = 16; o; o >>= 1) su += __shfl_xor_sync(0xffffffffu, su, o);
            ks[r][lane] = e / su;
        }
        __syncthreads();
        #pragma unroll
        for (int r = 0; r < 32; r++) {
            float vv = vs[r][lane];
            #pragma unroll
            for (int i = 0; i < 4; i++) acc[i] += ks[r][wp + 8 * i] * vv;
        }
        __syncthreads();
    }
    #pragma unroll
    for (int i = 0; i < 4; i++) {
        int e = wp + 8 * i;
        g_ctxp[(size_t)chunk * (B_ * HEADS_ * D_ * D_) +
               ((b * HEADS_ + head) * D_ + e) * D_ + lane] = acc[i];
    }
}

__global__ void ctx_comb()
{
    int idx = blockIdx.x * blockDim.x + threadIdx.x;  // B_*HEADS_*D_*D_
    if (idx >= B_ * HEADS_ * D_ * D_) return;
    float s = 0.0f;
    for (int ch = 0; ch < 16; ch++) s += g_ctxp[(size_t)ch * (B_ * HEADS_ * D_ * D_) + idx];
    g_ctx[idx] = s;
}

// ---------------- attn = softmax_N(q) @ ctx ---------------------------------
__global__ __launch_bounds__(256) void attn_kernel(const float* __restrict__ qkv,
                                                   float* __restrict__ out)
{
    __shared__ float ctxs[HEADS_ * D_ * D_];   // 8192 floats
    __shared__ float qs[C_], cm[C_], ci[C_];
    int b = blockIdx.y, ch = blockIdx.x;       // 16 x 64 (chunks of 64 rows)
    int tid = threadIdx.x;
    for (int j = tid; j < HEADS_ * D_ * D_; j += 256)
        ctxs[j] = g_ctx[b * HEADS_ * D_ * D_ + j];
    cm[tid] = g_cmax[b * C_ + tid];
    ci[tid] = g_cinv[b * C_ + tid];
    __syncthreads();
    int hh = tid >> 5, f = tid & 31;
    const float* ctxrow = ctxs + hh * (D_ * D_) + f;
    for (int j = 0; j < 64; j++) {
        size_t n = (size_t)b * N_ + ch * 64 + j;
        float qraw = qkv[n * (3 * C_) + tid];
        qs[tid] = __expf(qraw - cm[tid]) * ci[tid];
        __syncthreads();
        float s = 0.0f;
        #pragma unroll
        for (int e = 0; e < 32; e++) s += qs[hh * 32 + e] * ctxrow[e * 32];
        out[n * C_ + tid] = s;
        __syncthreads();
    }
}

// ---------------- CSDA ------------------------------------------------------
__global__ void cpool_part(const float* __restrict__ x3)
{
    int b = blockIdx.x, ch = blockIdx.y, c = threadIdx.x;
    const float* p = x3 + ((size_t)(b * N_ + ch * 128)) * C_ + c;
    float s = 0.0f, m = -1e30f;
    for (int i = 0; i < 128; i++) {
        float v = p[(size_t)i * C_];
        s += v; m = fmaxf(m, v);
    }
    g_cps[(b * 32 + ch) * C_ + c] = s;
    g_cpm[(b * 32 + ch) * C_ + c] = m;
}

__global__ void cpool_comb()
{
    int idx = blockIdx.x * blockDim.x + threadIdx.x;  // B_*C_
    if (idx >= B_ * C_) return;
    int b = idx >> 8, c = idx & 255;
    float s = 0.0f, m = -1e30f;
    for (int ch = 0; ch < 32; ch++) {
        s += g_cps[(b * 32 + ch) * C_ + c];
        m = fmaxf(m, g_cpm[(b * 32 + ch) * C_ + c]);
    }
    g_avg[idx] = s * (1.0f / N_);
    g_mx[idx] = m;
}

__global__ void ca_mlp(const float* __restrict__ w1, const float* __restrict__ w2)
{
    int b = blockIdx.x, t = threadIdx.x;
    __shared__ float hsum[16];
    if (t < 16) {
        float sa = 0.0f, sm = 0.0f;
        for (int c = 0; c < C_; c++) {
            float w = w1[t * C_ + c];
            sa += g_avg[b * C_ + c] * w;
            sm += g_mx[b * C_ + c] * w;
        }
        hsum[t] = fmaxf(sa, 0.0f) + fmaxf(sm, 0.0f);
    }
    __syncthreads();
    float acc = 0.0f;
    #pragma unroll
    for (int j = 0; j < 16; j++) acc += w2[t * 16 + j] * hsum[j];
    g_ca[b * C_ + t] = sigmf(acc);
}

__global__ void spool(const float* __restrict__ x3)
{
    int w = (blockIdx.x * blockDim.x + threadIdx.x) >> 5;
    int lane = threadIdx.x & 31;
    if (w >= ROWS_) return;
    int b = w >> 12;
    const float* r = x3 + (size_t)w * C_;
    const float* ca = g_ca + b * C_;
    float4 a = *(const float4*)(r + lane * 4);
    float4 c0 = *(const float4*)(ca + lane * 4);
    float4 bvals = *(const float4*)(r + 128 + lane * 4);
    float4 c1 = *(const float4*)(ca + 128 + lane * 4);
    float v0 = a.x * c0.x, v1 = a.y * c0.y, v2 = a.z * c0.z, v3 = a.w * c0.w;
    float v4 = bvals.x * c1.x, v5 = bvals.y * c1.y, v6 = bvals.z * c1.z, v7 = bvals.w * c1.w;
    float s = v0 + v1 + v2 + v3 + v4 + v5 + v6 + v7;
    float m = fmaxf(fmaxf(fmaxf(v0, v1), fmaxf(v2, v3)), fmaxf(fmaxf(v4, v5), fmaxf(v6, v7)));
    #pragma unroll
    for (int o = 16; o; o >>= 1) {
        s += __shfl_xor_sync(0xffffffffu, s, o);
        m = fmaxf(m, __shfl_xor_sync(0xffffffffu, m, o));
    }
    if (lane == 0) {
        g_sm[w] = s * (1.0f / C_);
        g_sx[w] = m;
    }
}

__global__ void conv7(const float* __restrict__ spw, const float* __restrict__ spb)
{
    int idx = blockIdx.x * blockDim.x + threadIdx.x;   // ROWS_
    if (idx >= ROWS_) return;
    int b = idx >> 12, n = idx & 4095;
    int h = n >> 6, w = n & 63;
    float acc = spb[0];
    #pragma unroll
    for (int ch = 0; ch < 2; ch++) {
        const float* src = ch ? g_sx : g_sm;
        const float* wp = spw + ch * 49;
        for (int ky = 0; ky < 7; ky++) {
            int y = h + ky - 3;
            if ((unsigned)y >= 64u) continue;
            for (int kx = 0; kx < 7; kx++) {
                int x = w + kx - 3;
                if ((unsigned)x >= 64u) continue;
                acc += src[(b << 12) + (y << 6) + x] * wp[ky * 7 + kx];
            }
        }
    }
    g_sa[idx] = sigmf(acc);
}

__global__ void final_scale(const float* __restrict__ x3, float* __restrict__ out)
{
    int idx = blockIdx.x * blockDim.x + threadIdx.x;   // ROWS_*64
    if (idx >= ROWS_ * 64) return;
    int c4 = idx & 63;
    int row = idx >> 6;
    int b = row >> 12;
    float4 v = *(const float4*)(x3 + (size_t)row * C_ + c4 * 4);
    float4 ca = *(const float4*)(g_ca + b * C_ + c4 * 4);
    float sa = g_sa[row];
    v.x *= ca.x * sa; v.y *= ca.y * sa; v.z *= ca.z * sa; v.w *= ca.w * sa;
    *(float4*)(out + (size_t)row * C_ + c4 * 4) = v;
}

// ---------------------------------------------------------------------------
extern "C" void kernel_launch(void* const* d_in, const int* in_sizes, int n_in,
                              void* d_out, int out_size)
{
    // Input mapping: optional scalar H, W at indices 1,2
    int p = (n_in >= 24 && in_sizes[1] == 1 && in_sizes[2] == 1) ? 3 : 1;
    const float* x      = (const float*)d_in[0];
    const float* n1_g   = (const float*)d_in[p + 0];
    const float* n1_b   = (const float*)d_in[p + 1];
    const float* sr_w   = (const float*)d_in[p + 2];
    const float* sr_b   = (const float*)d_in[p + 3];
    const float* an_g   = (const float*)d_in[p + 4];
    const float* an_b   = (const float*)d_in[p + 5];
    const float* qkv_w  = (const float*)d_in[p + 6];
    const float* proj_w = (const float*)d_in[p + 7];
    const float* proj_b = (const float*)d_in[p + 8];
    const float* n2_g   = (const float*)d_in[p + 9];
    const float* n2_b   = (const float*)d_in[p + 10];
    const float* fc1_w  = (const float*)d_in[p + 11];
    const float* fc1_b  = (const float*)d_in[p + 12];
    const float* dw_w   = (const float*)d_in[p + 13];
    const float* dw_b   = (const float*)d_in[p + 14];
    const float* fc2_w  = (const float*)d_in[p + 15];
    const float* fc2_b  = (const float*)d_in[p + 16];
    const float* ca_w1  = (const float*)d_in[p + 17];
    const float* ca_w2  = (const float*)d_in[p + 18];
    const float* sp_w   = (const float*)d_in[p + 19];
    const float* sp_b   = (const float*)d_in[p + 20];
    float* out = (float*)d_out;

    float *pxn, *pb1, *pb2, *pqkv, *ph1, *ph2;
    cudaGetSymbolAddress((void**)&pxn,  g_xn);
    cudaGetSymbolAddress((void**)&pb1,  g_b1);
    cudaGetSymbolAddress((void**)&pb2,  g_b2);
    cudaGetSymbolAddress((void**)&pqkv, g_qkv);
    cudaGetSymbolAddress((void**)&ph1,  g_h1);
    cudaGetSymbolAddress((void**)&ph2,  g_h2);

    const int TPB = 256;
    const int GEMM_SMEM = 4 * TILEF * 4;   // 2 stages x (A+B) x bytes = 73728
    cudaFuncSetAttribute(gemm_tf32, cudaFuncAttributeMaxDynamicSharedMemorySize,
                         GEMM_SMEM);

    // 1. xn = LN1(x)
    ln256<<<ROWS_ * 32 / TPB, TPB>>>(x, pxn, n1_g, n1_b);
    // 2. x_ = dwconv3(xn)          -> b1
    dwconv3<C_, false><<<(B_ * N_ * (C_ / 4) + TPB - 1) / TPB, TPB>>>(pxn, pb1, sr_w, sr_b);
    // 3. xa = xn + gelu(LN_act(x_)) (in-place b1)
    ln_gelu_add<<<ROWS_ * 32 / TPB, TPB>>>(pb1, pxn, an_g, an_b);
    // 4. qkv = xa @ qkv_w^T
    {
        dim3 g(3 * C_ / 128, ROWS_ / 128);
        gemm_tf32<<<g, TPB, GEMM_SMEM>>>(pb1, qkv_w, pqkv, ROWS_, 3 * C_, C_,
                                         nullptr, nullptr, nullptr);
    }
    // 5. q column-softmax stats
    {
        dim3 g(B_, 16);
        qsoft_part<<<g, TPB>>>(pqkv);
        qsoft_comb<<<(B_ * C_ + TPB - 1) / TPB, TPB>>>();
    }
    // 6. ctx = softmax_d(k)^T v
    {
        dim3 g(16, HEADS_, B_);
        ctx_kernel<<<g, TPB>>>(pqkv);
        ctx_comb<<<(B_ * HEADS_ * D_ * D_ + TPB - 1) / TPB, TPB>>>();
    }
    // 7. attn = softmax_N(q) @ ctx -> b2
    {
        dim3 g(64, B_);
        attn_kernel<<<g, TPB>>>(pqkv, pb2);
    }
    // 8. x2 = x + attn @ proj_w^T + proj_b + xn  -> b1
    {
        dim3 g(C_ / 128, ROWS_ / 128);
        gemm_tf32<<<g, TPB, GEMM_SMEM>>>(pb2, proj_w, pb1, ROWS_, C_, C_,
                                         proj_b, x, pxn);
    }
    // 9. ln2(x2) -> b2
    ln256<<<ROWS_ * 32 / TPB, TPB>>>(pb1, pb2, n2_g, n2_b);
    // 10. fc1 -> h1
    {
        dim3 g(HID_ / 128, ROWS_ / 128);
        gemm_tf32<<<g, TPB, GEMM_SMEM>>>(pb2, fc1_w, ph1, ROWS_, HID_, C_,
                                         fc1_b, nullptr, nullptr);
    }
    // 11. dwconv + gelu -> h2
    dwconv3<HID_, true><<<(B_ * N_ * (HID_ / 4) + TPB - 1) / TPB, TPB>>>(ph1, ph2, dw_w, dw_b);
    // 12. x3 = x2 + gelu_dw @ fc2_w^T + fc2_b  -> b2
    {
        dim3 g(C_ / 128, ROWS_ / 128);
        gemm_tf32<<<g, TPB, GEMM_SMEM>>>(ph2, fc2_w, pb2, ROWS_, C_, HID_,
                                         fc2_b, pb1, nullptr);
    }
    // 13. channel pools
    {
        dim3 g(B_, 32);
        cpool_part<<<g, TPB>>>(pb2);
        cpool_comb<<<(B_ * C_ + TPB - 1) / TPB, TPB>>>();
    }
    // 14. channel attention MLP
    ca_mlp<<<B_, TPB>>>(ca_w1, ca_w2);
    // 15. spatial pools of x3*ca
    spool<<<ROWS_ * 32 / TPB, TPB>>>(pb2);
    // 16. 7x7 spatial conv -> sa
    conv7<<<(ROWS_ + TPB - 1) / TPB, TPB>>>(sp_w, sp_b);
    // 17. out = x3 * ca * sa
    final_scale<<<(ROWS_ * 64 + TPB - 1) / TPB, TPB>>>(pb2, out);
}

// round 4
// speedup vs baseline: 2.7424x; 1.8670x over previous
#include <cuda_runtime.h>
#include <cuda_bf16.h>
#include <math.h>
#include <stdint.h>

// Problem constants
#define B_    16
#define N_    4096
#define C_    256
#define HEADS_ 8
#define D_    32
#define HID_  1024
#define ROWS_ 65536          // B_*N_

// ---------------- scratch (device globals; no allocation allowed) ----------
__device__ float g_xn  [ROWS_ * C_];        // norm1(x)
__device__ float g_b1  [ROWS_ * C_];        // dwconv -> x2
__device__ float g_b2  [ROWS_ * C_];        // x3
__device__ float g_qkv [ROWS_ * 3 * C_];    // qkv (fp32)
__device__ __nv_bfloat16 g_a16 [ROWS_ * C_];   // xa / attn / ln2 (bf16, reused)
__device__ __nv_bfloat16 g_h16a[ROWS_ * HID_]; // fc1 out (bf16)
__device__ __nv_bfloat16 g_h16b[ROWS_ * HID_]; // dwconv+gelu out (bf16)
__device__ __nv_bfloat16 g_w16 [786432];       // bf16 weights (qkv|proj|fc1|fc2)
#define W16_QKV  0
#define W16_PROJ 196608
#define W16_FC1  262144
#define W16_FC2  524288
__device__ float g_pm  [B_ * 16 * C_];
__device__ float g_ps  [B_ * 16 * C_];
__device__ float g_cmax[B_ * C_];
__device__ float g_cinv[B_ * C_];
__device__ float g_ctxp[16 * B_ * HEADS_ * D_ * D_];
__device__ float g_ctx [B_ * HEADS_ * D_ * D_];
__device__ float g_cps [B_ * 32 * C_];
__device__ float g_cpm [B_ * 32 * C_];
__device__ float g_avg [B_ * C_];
__device__ float g_mx  [B_ * C_];
__device__ float g_ca  [B_ * C_];
__device__ float g_sm  [ROWS_];
__device__ float g_sx  [ROWS_];
__device__ float g_sa  [ROWS_];

__device__ __forceinline__ float geluf(float x) {
    return 0.5f * x * (1.0f + erff(x * 0.70710678118654752440f));
}
__device__ __forceinline__ float sigmf(float x) {
    return 1.0f / (1.0f + __expf(-x));
}
__device__ __forceinline__ void store8(float* p, float4 v) { *(float4*)p = v; }
__device__ __forceinline__ void store8(__nv_bfloat16* p, float4 v) {
    __nv_bfloat162 h0 = __floats2bfloat162_rn(v.x, v.y);
    __nv_bfloat162 h1 = __floats2bfloat162_rn(v.z, v.w);
    uint2 u;
    u.x = *reinterpret_cast<uint32_t*>(&h0);
    u.y = *reinterpret_cast<uint32_t*>(&h1);
    *(uint2*)p = u;
}

// ---------------- fp32 -> bf16 weight conversion ----------------------------
__global__ void f2bf(const float* __restrict__ src, __nv_bfloat16* __restrict__ dst, int n)
{
    int i = blockIdx.x * blockDim.x + threadIdx.x;
    if (i * 2 + 1 < n) {
        float2 v = *(const float2*)(src + i * 2);
        __nv_bfloat162 h = __floats2bfloat162_rn(v.x, v.y);
        *(uint32_t*)(dst + i * 2) = *reinterpret_cast<uint32_t*>(&h);
    }
}

// ---------------- LayerNorm (256 wide), one warp per row --------------------
template <typename OutT>
__global__ void ln256(const float* __restrict__ in, OutT* __restrict__ out,
                      const float* __restrict__ g, const float* __restrict__ bt)
{
    int w = (blockIdx.x * blockDim.x + threadIdx.x) >> 5;
    int lane = threadIdx.x & 31;
    if (w >= ROWS_) return;
    const float* r = in + (size_t)w * C_;
    float4 a = *(const float4*)(r + lane * 4);
    float4 b = *(const float4*)(r + 128 + lane * 4);
    float s = a.x + a.y + a.z + a.w + b.x + b.y + b.z + b.w;
    float q = a.x*a.x + a.y*a.y + a.z*a.z + a.w*a.w
            + b.x*b.x + b.y*b.y + b.z*b.z + b.w*b.w;
    #pragma unroll
    for (int o = 16; o; o >>= 1) {
        s += __shfl_xor_sync(0xffffffffu, s, o);
        q += __shfl_xor_sync(0xffffffffu, q, o);
    }
    float mean = s * (1.0f / C_);
    float inv = rsqrtf(q * (1.0f / C_) - mean * mean + 1e-5f);
    float4 g0 = *(const float4*)(g + lane * 4);
    float4 g1 = *(const float4*)(g + 128 + lane * 4);
    float4 b0 = *(const float4*)(bt + lane * 4);
    float4 b1 = *(const float4*)(bt + 128 + lane * 4);
    float4 o0, o1;
    o0.x = (a.x - mean) * inv * g0.x + b0.x;
    o0.y = (a.y - mean) * inv * g0.y + b0.y;
    o0.z = (a.z - mean) * inv * g0.z + b0.z;
    o0.w = (a.w - mean) * inv * g0.w + b0.w;
    o1.x = (b.x - mean) * inv * g1.x + b1.x;
    o1.y = (b.y - mean) * inv * g1.y + b1.y;
    o1.z = (b.z - mean) * inv * g1.z + b1.z;
    o1.w = (b.w - mean) * inv * g1.w + b1.w;
    OutT* po = out + (size_t)w * C_;
    store8(po + lane * 4, o0);
    store8(po + 128 + lane * 4, o1);
}

// xa16 = bf16( xn + gelu(LN(buf)) )
__global__ void ln_gelu_add(const float* __restrict__ buf, const float* __restrict__ xn,
                            __nv_bfloat16* __restrict__ out,
                            const float* __restrict__ g, const float* __restrict__ bt)
{
    int w = (blockIdx.x * blockDim.x + threadIdx.x) >> 5;
    int lane = threadIdx.x & 31;
    if (w >= ROWS_) return;
    const float* r = buf + (size_t)w * C_;
    const float* xr = xn + (size_t)w * C_;
    float4 a = *(const float4*)(r + lane * 4);
    float4 b = *(const float4*)(r + 128 + lane * 4);
    float s = a.x + a.y + a.z + a.w + b.x + b.y + b.z + b.w;
    float q = a.x*a.x + a.y*a.y + a.z*a.z + a.w*a.w
            + b.x*b.x + b.y*b.y + b.z*b.z + b.w*b.w;
    #pragma unroll
    for (int o = 16; o; o >>= 1) {
        s += __shfl_xor_sync(0xffffffffu, s, o);
        q += __shfl_xor_sync(0xffffffffu, q, o);
    }
    float mean = s * (1.0f / C_);
    float inv = rsqrtf(q * (1.0f / C_) - mean * mean + 1e-5f);
    float4 g0 = *(const float4*)(g + lane * 4);
    float4 g1 = *(const float4*)(g + 128 + lane * 4);
    float4 b0 = *(const float4*)(bt + lane * 4);
    float4 b1 = *(const float4*)(bt + 128 + lane * 4);
    float4 x0 = *(const float4*)(xr + lane * 4);
    float4 x1 = *(const float4*)(xr + 128 + lane * 4);
    float4 o0, o1;
    o0.x = x0.x + geluf((a.x - mean) * inv * g0.x + b0.x);
    o0.y = x0.y + geluf((a.y - mean) * inv * g0.y + b0.y);
    o0.z = x0.z + geluf((a.z - mean) * inv * g0.z + b0.z);
    o0.w = x0.w + geluf((a.w - mean) * inv * g0.w + b0.w);
    o1.x = x1.x + geluf((b.x - mean) * inv * g1.x + b1.x);
    o1.y = x1.y + geluf((b.y - mean) * inv * g1.y + b1.y);
    o1.z = x1.z + geluf((b.z - mean) * inv * g1.z + b1.z);
    o1.w = x1.w + geluf((b.w - mean) * inv * g1.w + b1.w);
    __nv_bfloat16* po = out + (size_t)w * C_;
    store8(po + lane * 4, o0);
    store8(po + 128 + lane * 4, o1);
}

// ---------------- depthwise 3x3 fp32 (C=256 path) ---------------------------
__global__ void dwconv3_f32(const float* __restrict__ in, float* __restrict__ out,
                            const float* __restrict__ w, const float* __restrict__ bias)
{
    const int CH = C_, C4 = CH / 4;
    int idx = blockIdx.x * blockDim.x + threadIdx.x;
    if (idx >= B_ * N_ * C4) return;
    int c4 = idx % C4;
    int n  = (idx / C4) % N_;
    int b  = idx / (C4 * N_);
    int h = n >> 6, wp = n & 63;
    int c0 = c4 * 4;
    float wr[4][9];
    #pragma unroll
    for (int i = 0; i < 4; i++)
        #pragma unroll
        for (int k = 0; k < 9; k++)
            wr[i][k] = w[(c0 + i) * 9 + k];
    float4 acc;
    acc.x = bias[c0]; acc.y = bias[c0 + 1]; acc.z = bias[c0 + 2]; acc.w = bias[c0 + 3];
    #pragma unroll
    for (int dy = -1; dy <= 1; dy++) {
        int hh = h + dy;
        if ((unsigned)hh >= 64u) continue;
        #pragma unroll
        for (int dx = -1; dx <= 1; dx++) {
            int ww = wp + dx;
            if ((unsigned)ww >= 64u) continue;
            int k = (dy + 1) * 3 + (dx + 1);
            float4 v = *(const float4*)(in + ((size_t)(b * N_ + hh * 64 + ww)) * CH + c0);
            acc.x += v.x * wr[0][k];
            acc.y += v.y * wr[1][k];
            acc.z += v.z * wr[2][k];
            acc.w += v.w * wr[3][k];
        }
    }
    *(float4*)(out + ((size_t)(b * N_ + n)) * CH + c0) = acc;
}

// ---------------- depthwise 3x3 bf16 in/out + gelu (HID=1024 path) ----------
__global__ void dwconv3_bf16(const __nv_bfloat16* __restrict__ in,
                             __nv_bfloat16* __restrict__ out,
                             const float* __restrict__ w, const float* __restrict__ bias)
{
    const int CH = HID_, C4 = CH / 4;
    int idx = blockIdx.x * blockDim.x + threadIdx.x;
    if (idx >= B_ * N_ * C4) return;
    int c4 = idx % C4;
    int n  = (idx / C4) % N_;
    int b  = idx / (C4 * N_);
    int h = n >> 6, wp = n & 63;
    int c0 = c4 * 4;
    float wr[4][9];
    #pragma unroll
    for (int i = 0; i < 4; i++)
        #pragma unroll
        for (int k = 0; k < 9; k++)
            wr[i][k] = w[(c0 + i) * 9 + k];
    float a0 = bias[c0], a1 = bias[c0 + 1], a2 = bias[c0 + 2], a3 = bias[c0 + 3];
    #pragma unroll
    for (int dy = -1; dy <= 1; dy++) {
        int hh = h + dy;
        if ((unsigned)hh >= 64u) continue;
        #pragma unroll
        for (int dx = -1; dx <= 1; dx++) {
            int ww = wp + dx;
            if ((unsigned)ww >= 64u) continue;
            int k = (dy + 1) * 3 + (dx + 1);
            uint2 raw = *(const uint2*)(in + ((size_t)(b * N_ + hh * 64 + ww)) * CH + c0);
            float2 f0 = __bfloat1622float2(*reinterpret_cast<__nv_bfloat162*>(&raw.x));
            float2 f1 = __bfloat1622float2(*reinterpret_cast<__nv_bfloat162*>(&raw.y));
            a0 += f0.x * wr[0][k];
            a1 += f0.y * wr[1][k];
            a2 += f1.x * wr[2][k];
            a3 += f1.y * wr[3][k];
        }
    }
    float4 o = make_float4(geluf(a0), geluf(a1), geluf(a2), geluf(a3));
    store8(out + ((size_t)(b * N_ + n)) * CH + c0, o);
}

// ---------------- BF16 tensor-core GEMM: C = A[M,K] @ W[N,K]^T --------------
// 128x128x64 tiles, 8 warps (2m x 4n), warp 64x32 via m16n8k16, 2-stage cp.async.
#define HSTR  72                  // halves per smem row (64 + 8 pad)
#define HTILE (128 * HSTR)        // halves per stage per matrix

__device__ __forceinline__ void cp16(uint32_t d, const void* s) {
    asm volatile("cp.async.cg.shared.global [%0], [%1], 16;" :: "r"(d), "l"(s));
}

template <typename OutT>
__global__ __launch_bounds__(256, 2)
void gemm_bf16(const __nv_bfloat16* __restrict__ A, const __nv_bfloat16* __restrict__ W,
               OutT* __restrict__ Cout, int M, int N, int K,
               const float* __restrict__ bias,
               const float* __restrict__ r1, const float* __restrict__ r2)
{
    extern __shared__ __nv_bfloat16 sh16[];
    __nv_bfloat16* Ash = sh16;                 // [2][128][HSTR]
    __nv_bfloat16* Bsh = sh16 + 2 * HTILE;

    int tid = threadIdx.x;
    int warp = tid >> 5, lane = tid & 31;
    int wm = warp >> 2, wn = warp & 3;
    int bm = blockIdx.y * 128, bn = blockIdx.x * 128;
    int gr = lane >> 2, gc = lane & 3;

    float acc[4][4][4];
    #pragma unroll
    for (int i = 0; i < 4; i++)
        #pragma unroll
        for (int j = 0; j < 4; j++)
            #pragma unroll
            for (int q = 0; q < 4; q++) acc[i][j][q] = 0.0f;

    int KT = K >> 6;

    int ldr = tid >> 3;            // 0..31 (x4 iters -> 128 rows)
    int ldc = (tid & 7) * 8;       // half offset within 64-wide k-tile
    const __nv_bfloat16* Abase = A + (size_t)(bm + ldr) * K + ldc;
    const __nv_bfloat16* Wbase = W + (size_t)(bn + ldr) * K + ldc;
    uint32_t sAd = (uint32_t)__cvta_generic_to_shared(&Ash[ldr * HSTR + ldc]);
    uint32_t sBd = (uint32_t)__cvta_generic_to_shared(&Bsh[ldr * HSTR + ldc]);
    const uint32_t stageB = HTILE * 2;        // bytes per stage
    const uint32_t rowB   = 32 * HSTR * 2;    // bytes per 32-row group

    #define LOAD_STAGE(st, kb) do {                                            \
        uint32_t so = (st) * stageB;                                           \
        size_t go = (size_t)(kb) * 64;                                         \
        _Pragma("unroll")                                                      \
        for (int it = 0; it < 4; it++) {                                       \
            cp16(sAd + so + it * rowB, Abase + (size_t)(it * 32) * K + go);    \
            cp16(sBd + so + it * rowB, Wbase + (size_t)(it * 32) * K + go);    \
        }                                                                      \
        asm volatile("cp.async.commit_group;");                                \
    } while (0)

    LOAD_STAGE(0, 0);
    int st = 0;
    for (int kb = 0; kb < KT; kb++) {
        if (kb + 1 < KT) {
            LOAD_STAGE(st ^ 1, kb + 1);
            asm volatile("cp.async.wait_group 1;");
        } else {
            asm volatile("cp.async.wait_group 0;");
        }
        __syncthreads();

        const uint32_t* As32 = reinterpret_cast<const uint32_t*>(Ash + st * HTILE);
        const uint32_t* Bs32 = reinterpret_cast<const uint32_t*>(Bsh + st * HTILE);
        #pragma unroll
        for (int ks = 0; ks < 4; ks++) {
            uint32_t a[4][4], b[4][2];
            #pragma unroll
            for (int i = 0; i < 4; i++) {
                int base = (wm * 64 + i * 16 + gr) * (HSTR / 2) + ks * 8 + gc;
                a[i][0] = As32[base];
                a[i][1] = As32[base + 8 * (HSTR / 2)];
                a[i][2] = As32[base + 4];
                a[i][3] = As32[base + 8 * (HSTR / 2) + 4];
            }
            #pragma unroll
            for (int j = 0; j < 4; j++) {
                int base = (wn * 32 + j * 8 + gr) * (HSTR / 2) + ks * 8 + gc;
                b[j][0] = Bs32[base];
                b[j][1] = Bs32[base + 4];
            }
            #pragma unroll
            for (int i = 0; i < 4; i++)
                #pragma unroll
                for (int j = 0; j < 4; j++)
                    asm volatile(
                        "mma.sync.aligned.m16n8k16.row.col.f32.bf16.bf16.f32 "
                        "{%0,%1,%2,%3}, {%4,%5,%6,%7}, {%8,%9}, {%0,%1,%2,%3};"
                        : "+f"(acc[i][j][0]), "+f"(acc[i][j][1]),
                          "+f"(acc[i][j][2]), "+f"(acc[i][j][3])
                        : "r"(a[i][0]), "r"(a[i][1]), "r"(a[i][2]), "r"(a[i][3]),
                          "r"(b[j][0]), "r"(b[j][1]));
        }
        __syncthreads();
        st ^= 1;
    }

    // -------- epilogue ----------
    #pragma unroll
    for (int i = 0; i < 4; i++) {
        int row0 = bm + wm * 64 + i * 16 + gr;
        #pragma unroll
        for (int j = 0; j < 4; j++) {
            int col = bn + wn * 32 + j * 8 + gc * 2;
            float bx = 0.f, by = 0.f;
            if (bias) { bx = bias[col]; by = bias[col + 1]; }
            size_t o0 = (size_t)row0 * N + col;
            size_t o1 = (size_t)(row0 + 8) * N + col;
            float v0 = acc[i][j][0] + bx, v1 = acc[i][j][1] + by;
            float v2 = acc[i][j][2] + bx, v3 = acc[i][j][3] + by;
            if (r1) {
                float2 p0 = *(const float2*)(r1 + o0);
                float2 p1 = *(const float2*)(r1 + o1);
                v0 += p0.x; v1 += p0.y; v2 += p1.x; v3 += p1.y;
            }
            if (r2) {
                float2 p0 = *(const float2*)(r2 + o0);
                float2 p1 = *(const float2*)(r2 + o1);
                v0 += p0.x; v1 += p0.y; v2 += p1.x; v3 += p1.y;
            }
            if constexpr (sizeof(OutT) == 4) {
                *(float2*)((float*)Cout + o0) = make_float2(v0, v1);
                *(float2*)((float*)Cout + o1) = make_float2(v2, v3);
            } else {
                __nv_bfloat162 h0 = __floats2bfloat162_rn(v0, v1);
                __nv_bfloat162 h1 = __floats2bfloat162_rn(v2, v3);
                *(uint32_t*)((__nv_bfloat16*)Cout + o0) = *reinterpret_cast<uint32_t*>(&h0);
                *(uint32_t*)((__nv_bfloat16*)Cout + o1) = *reinterpret_cast<uint32_t*>(&h1);
            }
        }
    }
}

// ---------------- q softmax over tokens: per-(b,c) online partials ----------
__global__ void qsoft_part(const float* __restrict__ qkv)
{
    int b = blockIdx.x, ch = blockIdx.y, c = threadIdx.x;
    const float* p = qkv + ((size_t)(b * N_ + ch * 256)) * (3 * C_) + c;
    float m = -1e30f, s = 0.0f;
    for (int i = 0; i < 256; i++) {
        float v = p[(size_t)i * (3 * C_)];
        float nm = fmaxf(m, v);
        s = s * __expf(m - nm) + __expf(v - nm);
        m = nm;
    }
    g_pm[(b * 16 + ch) * C_ + c] = m;
    g_ps[(b * 16 + ch) * C_ + c] = s;
}

__global__ void qsoft_comb()
{
    int idx = blockIdx.x * blockDim.x + threadIdx.x;
    if (idx >= B_ * C_) return;
    int b = idx >> 8, c = idx & 255;
    float M = -1e30f;
    for (int ch = 0; ch < 16; ch++) M = fmaxf(M, g_pm[(b * 16 + ch) * C_ + c]);
    float S = 0.0f;
    for (int ch = 0; ch < 16; ch++)
        S += g_ps[(b * 16 + ch) * C_ + c] * __expf(g_pm[(b * 16 + ch) * C_ + c] - M);
    g_cmax[idx] = M;
    g_cinv[idx] = 1.0f / S;
}

// ---------------- ctx = softmax_d(k)^T @ v ----------------------------------
__global__ __launch_bounds__(256) void ctx_kernel(const float* __restrict__ qkv)
{
    int chunk = blockIdx.x;
    int head  = blockIdx.y;
    int b     = blockIdx.z;
    __shared__ float ks[32][33];
    __shared__ float vs[32][33];
    int tid = threadIdx.x, lane = tid & 31, wp = tid >> 5;
    float acc[4] = {0.f, 0.f, 0.f, 0.f};
    for (int it = 0; it < 8; it++) {
        int nb = chunk * 256 + it * 32;
        #pragma unroll
        for (int j = 0; j < 8; j++) {
            int id = tid + 256 * j;
            int r = id >> 6, inner = id & 63;
            const float* src = qkv + ((size_t)(b * N_ + nb + r)) * (3 * C_) + C_ + head * D_;
            if (inner < 32) ks[r][inner] = src[inner];
            else            vs[r][inner - 32] = src[C_ + inner - 32];
        }
        __syncthreads();
        #pragma unroll
        for (int rr = 0; rr < 4; rr++) {
            int r = wp * 4 + rr;
            float v = ks[r][lane];
            float mx = v;
            #pragma unroll
            for (int o = 16; o; o >>= 1) mx = fmaxf(mx, __shfl_xor_sync(0xffffffffu, mx, o));
            float e = __expf(v - mx);
            float su = e;
            #pragma unroll
            for (int o = 16; o; o >>= 1) su += __shfl_xor_sync(0xffffffffu, su, o);
            ks[r][lane] = e / su;
        }
        __syncthreads();
        #pragma unroll
        for (int r = 0; r < 32; r++) {
            float vv = vs[r][lane];
            #pragma unroll
            for (int i = 0; i < 4; i++) acc[i] += ks[r][wp + 8 * i] * vv;
        }
        __syncthreads();
    }
    #pragma unroll
    for (int i = 0; i < 4; i++) {
        int e = wp + 8 * i;
        g_ctxp[(size_t)chunk * (B_ * HEADS_ * D_ * D_) +
               ((b * HEADS_ + head) * D_ + e) * D_ + lane] = acc[i];
    }
}

__global__ void ctx_comb()
{
    int idx = blockIdx.x * blockDim.x + threadIdx.x;
    if (idx >= B_ * HEADS_ * D_ * D_) return;
    float s = 0.0f;
    for (int ch = 0; ch < 16; ch++) s += g_ctxp[(size_t)ch * (B_ * HEADS_ * D_ * D_) + idx];
    g_ctx[idx] = s;
}

// ---------------- attn = softmax_N(q) @ ctx  (bf16 out) ---------------------
__global__ __launch_bounds__(256) void attn_kernel(const float* __restrict__ qkv,
                                                   __nv_bfloat16* __restrict__ out)
{
    __shared__ float ctxs[HEADS_ * D_ * D_];
    __shared__ float qs[C_], cm[C_], ci[C_];
    int b = blockIdx.y, ch = blockIdx.x;
    int tid = threadIdx.x;
    for (int j = tid; j < HEADS_ * D_ * D_; j += 256)
        ctxs[j] = g_ctx[b * HEADS_ * D_ * D_ + j];
    cm[tid] = g_cmax[b * C_ + tid];
    ci[tid] = g_cinv[b * C_ + tid];
    __syncthreads();
    int hh = tid >> 5, f = tid & 31;
    const float* ctxrow = ctxs + hh * (D_ * D_) + f;
    for (int j = 0; j < 64; j++) {
        size_t n = (size_t)b * N_ + ch * 64 + j;
        float qraw = qkv[n * (3 * C_) + tid];
        qs[tid] = __expf(qraw - cm[tid]) * ci[tid];
        __syncthreads();
        float s = 0.0f;
        #pragma unroll
        for (int e = 0; e < 32; e++) s += qs[hh * 32 + e] * ctxrow[e * 32];
        out[n * C_ + tid] = __float2bfloat16_rn(s);
        __syncthreads();
    }
}

// ---------------- CSDA ------------------------------------------------------
__global__ void cpool_part(const float* __restrict__ x3)
{
    int b = blockIdx.x, ch = blockIdx.y, c = threadIdx.x;
    const float* p = x3 + ((size_t)(b * N_ + ch * 128)) * C_ + c;
    float s = 0.0f, m = -1e30f;
    for (int i = 0; i < 128; i++) {
        float v = p[(size_t)i * C_];
        s += v; m = fmaxf(m, v);
    }
    g_cps[(b * 32 + ch) * C_ + c] = s;
    g_cpm[(b * 32 + ch) * C_ + c] = m;
}

__global__ void cpool_comb()
{
    int idx = blockIdx.x * blockDim.x + threadIdx.x;
    if (idx >= B_ * C_) return;
    int b = idx >> 8, c = idx & 255;
    float s = 0.0f, m = -1e30f;
    for (int ch = 0; ch < 32; ch++) {
        s += g_cps[(b * 32 + ch) * C_ + c];
        m = fmaxf(m, g_cpm[(b * 32 + ch) * C_ + c]);
    }
    g_avg[idx] = s * (1.0f / N_);
    g_mx[idx] = m;
}

__global__ void ca_mlp(const float* __restrict__ w1, const float* __restrict__ w2)
{
    int b = blockIdx.x, t = threadIdx.x;
    __shared__ float hsum[16];
    if (t < 16) {
        float sa = 0.0f, sm = 0.0f;
        for (int c = 0; c < C_; c++) {
            float w = w1[t * C_ + c];
            sa += g_avg[b * C_ + c] * w;
            sm += g_mx[b * C_ + c] * w;
        }
        hsum[t] = fmaxf(sa, 0.0f) + fmaxf(sm, 0.0f);
    }
    __syncthreads();
    float acc = 0.0f;
    #pragma unroll
    for (int j = 0; j < 16; j++) acc += w2[t * 16 + j] * hsum[j];
    g_ca[b * C_ + t] = sigmf(acc);
}

__global__ void spool(const float* __restrict__ x3)
{
    int w = (blockIdx.x * blockDim.x + threadIdx.x) >> 5;
    int lane = threadIdx.x & 31;
    if (w >= ROWS_) return;
    int b = w >> 12;
    const float* r = x3 + (size_t)w * C_;
    const float* ca = g_ca + b * C_;
    float4 a = *(const float4*)(r + lane * 4);
    float4 c0 = *(const float4*)(ca + lane * 4);
    float4 bvals = *(const float4*)(r + 128 + lane * 4);
    float4 c1 = *(const float4*)(ca + 128 + lane * 4);
    float v0 = a.x * c0.x, v1 = a.y * c0.y, v2 = a.z * c0.z, v3 = a.w * c0.w;
    float v4 = bvals.x * c1.x, v5 = bvals.y * c1.y, v6 = bvals.z * c1.z, v7 = bvals.w * c1.w;
    float s = v0 + v1 + v2 + v3 + v4 + v5 + v6 + v7;
    float m = fmaxf(fmaxf(fmaxf(v0, v1), fmaxf(v2, v3)), fmaxf(fmaxf(v4, v5), fmaxf(v6, v7)));
    #pragma unroll
    for (int o = 16; o; o >>= 1) {
        s += __shfl_xor_sync(0xffffffffu, s, o);
        m = fmaxf(m, __shfl_xor_sync(0xffffffffu, m, o));
    }
    if (lane == 0) {
        g_sm[w] = s * (1.0f / C_);
        g_sx[w] = m;
    }
}

__global__ void conv7(const float* __restrict__ spw, const float* __restrict__ spb)
{
    int idx = blockIdx.x * blockDim.x + threadIdx.x;
    if (idx >= ROWS_) return;
    int b = idx >> 12, n = idx & 4095;
    int h = n >> 6, w = n & 63;
    float acc = spb[0];
    #pragma unroll
    for (int ch = 0; ch < 2; ch++) {
        const float* src = ch ? g_sx : g_sm;
        const float* wp = spw + ch * 49;
        for (int ky = 0; ky < 7; ky++) {
            int y = h + ky - 3;
            if ((unsigned)y >= 64u) continue;
            for (int kx = 0; kx < 7; kx++) {
                int x = w + kx - 3;
                if ((unsigned)x >= 64u) continue;
                acc += src[(b << 12) + (y << 6) + x] * wp[ky * 7 + kx];
            }
        }
    }
    g_sa[idx] = sigmf(acc);
}

__global__ void final_scale(const float* __restrict__ x3, float* __restrict__ out)
{
    int idx = blockIdx.x * blockDim.x + threadIdx.x;
    if (idx >= ROWS_ * 64) return;
    int c4 = idx & 63;
    int row = idx >> 6;
    int b = row >> 12;
    float4 v = *(const float4*)(x3 + (size_t)row * C_ + c4 * 4);
    float4 ca = *(const float4*)(g_ca + b * C_ + c4 * 4);
    float sa = g_sa[row];
    v.x *= ca.x * sa; v.y *= ca.y * sa; v.z *= ca.z * sa; v.w *= ca.w * sa;
    *(float4*)(out + (size_t)row * C_ + c4 * 4) = v;
}

// ---------------------------------------------------------------------------
extern "C" void kernel_launch(void* const* d_in, const int* in_sizes, int n_in,
                              void* d_out, int out_size)
{
    int p = (n_in >= 24 && in_sizes[1] == 1 && in_sizes[2] == 1) ? 3 : 1;
    const float* x      = (const float*)d_in[0];
    const float* n1_g   = (const float*)d_in[p + 0];
    const float* n1_b   = (const float*)d_in[p + 1];
    const float* sr_w   = (const float*)d_in[p + 2];
    const float* sr_b   = (const float*)d_in[p + 3];
    const float* an_g   = (const float*)d_in[p + 4];
    const float* an_b   = (const float*)d_in[p + 5];
    const float* qkv_w  = (const float*)d_in[p + 6];
    const float* proj_w = (const float*)d_in[p + 7];
    const float* proj_b = (const float*)d_in[p + 8];
    const float* n2_g   = (const float*)d_in[p + 9];
    const float* n2_b   = (const float*)d_in[p + 10];
    const float* fc1_w  = (const float*)d_in[p + 11];
    const float* fc1_b  = (const float*)d_in[p + 12];
    const float* dw_w   = (const float*)d_in[p + 13];
    const float* dw_b   = (const float*)d_in[p + 14];
    const float* fc2_w  = (const float*)d_in[p + 15];
    const float* fc2_b  = (const float*)d_in[p + 16];
    const float* ca_w1  = (const float*)d_in[p + 17];
    const float* ca_w2  = (const float*)d_in[p + 18];
    const float* sp_w   = (const float*)d_in[p + 19];
    const float* sp_b   = (const float*)d_in[p + 20];
    float* out = (float*)d_out;

    float *pxn, *pb1, *pb2, *pqkv;
    __nv_bfloat16 *pa16, *ph16a, *ph16b, *pw16;
    cudaGetSymbolAddress((void**)&pxn,   g_xn);
    cudaGetSymbolAddress((void**)&pb1,   g_b1);
    cudaGetSymbolAddress((void**)&pb2,   g_b2);
    cudaGetSymbolAddress((void**)&pqkv,  g_qkv);
    cudaGetSymbolAddress((void**)&pa16,  g_a16);
    cudaGetSymbolAddress((void**)&ph16a, g_h16a);
    cudaGetSymbolAddress((void**)&ph16b, g_h16b);
    cudaGetSymbolAddress((void**)&pw16,  g_w16);

    const int TPB = 256;
    const int GEMM_SMEM = 4 * HTILE * 2;   // 73728 bytes
    cudaFuncSetAttribute(gemm_bf16<float>, cudaFuncAttributeMaxDynamicSharedMemorySize,
                         GEMM_SMEM);
    cudaFuncSetAttribute(gemm_bf16<__nv_bfloat16>, cudaFuncAttributeMaxDynamicSharedMemorySize,
                         GEMM_SMEM);

    // 0. bf16 weight conversion
    f2bf<<<(196608 / 2 + TPB - 1) / TPB, TPB>>>(qkv_w,  pw16 + W16_QKV,  196608);
    f2bf<<<(65536  / 2 + TPB - 1) / TPB, TPB>>>(proj_w, pw16 + W16_PROJ, 65536);
    f2bf<<<(262144 / 2 + TPB - 1) / TPB, TPB>>>(fc1_w,  pw16 + W16_FC1,  262144);
    f2bf<<<(262144 / 2 + TPB - 1) / TPB, TPB>>>(fc2_w,  pw16 + W16_FC2,  262144);

    // 1. xn = LN1(x)
    ln256<float><<<ROWS_ * 32 / TPB, TPB>>>(x, pxn, n1_g, n1_b);
    // 2. x_ = dwconv3(xn) -> b1
    dwconv3_f32<<<(B_ * N_ * (C_ / 4) + TPB - 1) / TPB, TPB>>>(pxn, pb1, sr_w, sr_b);
    // 3. xa16 = bf16(xn + gelu(LN_act(x_)))
    ln_gelu_add<<<ROWS_ * 32 / TPB, TPB>>>(pb1, pxn, pa16, an_g, an_b);
    // 4. qkv = xa @ qkv_w^T
    {
        dim3 g(3 * C_ / 128, ROWS_ / 128);
        gemm_bf16<float><<<g, TPB, GEMM_SMEM>>>(pa16, pw16 + W16_QKV, pqkv,
                                                ROWS_, 3 * C_, C_, nullptr, nullptr, nullptr);
    }
    // 5. q column-softmax stats
    {
        dim3 g(B_, 16);
        qsoft_part<<<g, TPB>>>(pqkv);
        qsoft_comb<<<(B_ * C_ + TPB - 1) / TPB, TPB>>>();
    }
    // 6. ctx = softmax_d(k)^T v
    {
        dim3 g(16, HEADS_, B_);
        ctx_kernel<<<g, TPB>>>(pqkv);
        ctx_comb<<<(B_ * HEADS_ * D_ * D_ + TPB - 1) / TPB, TPB>>>();
    }
    // 7. attn = softmax_N(q) @ ctx -> a16 (bf16)
    {
        dim3 g(64, B_);
        attn_kernel<<<g, TPB>>>(pqkv, pa16);
    }
    // 8. x2 = x + attn @ proj_w^T + proj_b + xn -> b1
    {
        dim3 g(C_ / 128, ROWS_ / 128);
        gemm_bf16<float><<<g, TPB, GEMM_SMEM>>>(pa16, pw16 + W16_PROJ, pb1,
                                                ROWS_, C_, C_, proj_b, x, pxn);
    }
    // 9. ln2(x2) -> a16 (bf16)
    ln256<__nv_bfloat16><<<ROWS_ * 32 / TPB, TPB>>>(pb1, pa16, n2_g, n2_b);
    // 10. fc1 -> h16a (bf16)
    {
        dim3 g(HID_ / 128, ROWS_ / 128);
        gemm_bf16<__nv_bfloat16><<<g, TPB, GEMM_SMEM>>>(pa16, pw16 + W16_FC1, ph16a,
                                                        ROWS_, HID_, C_, fc1_b, nullptr, nullptr);
    }
    // 11. dwconv + gelu (bf16) -> h16b
    dwconv3_bf16<<<(B_ * N_ * (HID_ / 4) + TPB - 1) / TPB, TPB>>>(ph16a, ph16b, dw_w, dw_b);
    // 12. x3 = x2 + gelu_dw @ fc2_w^T + fc2_b -> b2
    {
        dim3 g(C_ / 128, ROWS_ / 128);
        gemm_bf16<float><<<g, TPB, GEMM_SMEM>>>(ph16b, pw16 + W16_FC2, pb2,
                                                ROWS_, C_, HID_, fc2_b, pb1, nullptr);
    }
    // 13. channel pools
    {
        dim3 g(B_, 32);
        cpool_part<<<g, TPB>>>(pb2);
        cpool_comb<<<(B_ * C_ + TPB - 1) / TPB, TPB>>>();
    }
    // 14. channel attention MLP
    ca_mlp<<<B_, TPB>>>(ca_w1, ca_w2);
    // 15. spatial pools of x3*ca
    spool<<<ROWS_ * 32 / TPB, TPB>>>(pb2);
    // 16. 7x7 spatial conv -> sa
    conv7<<<(ROWS_ + TPB - 1) / TPB, TPB>>>(sp_w, sp_b);
    // 17. out = x3 * ca * sa
    final_scale<<<(ROWS_ * 64 + TPB - 1) / TPB, TPB>>>(pb2, out);
}

// round 5
// speedup vs baseline: 2.9121x; 1.0619x over previous
#include <cuda_runtime.h>
#include <cuda_bf16.h>
#include <math.h>
#include <stdint.h>

// Problem constants
#define B_    16
#define N_    4096
#define C_    256
#define HEADS_ 8
#define D_    32
#define HID_  1024
#define ROWS_ 65536          // B_*N_

// ---------------- scratch (device globals; no allocation allowed) ----------
__device__ float g_xn  [ROWS_ * C_];           // norm1(x)
__device__ float g_b1  [ROWS_ * C_];           // x2
__device__ float g_b2  [ROWS_ * C_];           // x3
__device__ __nv_bfloat16 g_qkv16[ROWS_ * 3 * C_]; // qkv (bf16)
__device__ __nv_bfloat16 g_a16 [ROWS_ * C_];   // xa / attn / ln2 (bf16, reused)
__device__ __nv_bfloat16 g_h16a[ROWS_ * HID_]; // fc1 out (bf16)
__device__ __nv_bfloat16 g_h16b[ROWS_ * HID_]; // dwconv+gelu out (bf16)
__device__ __nv_bfloat16 g_w16 [786432];       // bf16 weights (qkv|proj|fc1|fc2)
#define W16_QKV  0
#define W16_PROJ 196608
#define W16_FC1  262144
#define W16_FC2  524288
__device__ float g_pm  [B_ * 16 * C_];
__device__ float g_ps  [B_ * 16 * C_];
__device__ float g_cmax[B_ * C_];
__device__ float g_cinv[B_ * C_];
__device__ float g_ctxp[16 * B_ * HEADS_ * D_ * D_];
__device__ float g_ctx [B_ * HEADS_ * D_ * D_];
__device__ float g_cps [B_ * 32 * C_];
__device__ float g_cpm [B_ * 32 * C_];
__device__ float g_avg [B_ * C_];
__device__ float g_mx  [B_ * C_];
__device__ float g_ca  [B_ * C_];
__device__ float g_sm  [ROWS_];
__device__ float g_sx  [ROWS_];
__device__ float g_sa  [ROWS_];

__device__ __forceinline__ float geluf(float x) {
    return 0.5f * x * (1.0f + erff(x * 0.70710678118654752440f));
}
__device__ __forceinline__ float sigmf(float x) {
    return 1.0f / (1.0f + __expf(-x));
}
__device__ __forceinline__ void store8(float* p, float4 v) { *(float4*)p = v; }
__device__ __forceinline__ void store8(__nv_bfloat16* p, float4 v) {
    __nv_bfloat162 h0 = __floats2bfloat162_rn(v.x, v.y);
    __nv_bfloat162 h1 = __floats2bfloat162_rn(v.z, v.w);
    uint2 u;
    u.x = *reinterpret_cast<uint32_t*>(&h0);
    u.y = *reinterpret_cast<uint32_t*>(&h1);
    *(uint2*)p = u;
}

// ---------------- fp32 -> bf16 weight conversion ----------------------------
__global__ void f2bf(const float* __restrict__ src, __nv_bfloat16* __restrict__ dst, int n)
{
    int i = blockIdx.x * blockDim.x + threadIdx.x;
    if (i * 2 + 1 < n) {
        float2 v = *(const float2*)(src + i * 2);
        __nv_bfloat162 h = __floats2bfloat162_rn(v.x, v.y);
        *(uint32_t*)(dst + i * 2) = *reinterpret_cast<uint32_t*>(&h);
    }
}

// ---------------- LayerNorm (256 wide), one warp per row --------------------
template <typename OutT>
__global__ void ln256(const float* __restrict__ in, OutT* __restrict__ out,
                      const float* __restrict__ g, const float* __restrict__ bt)
{
    int w = (blockIdx.x * blockDim.x + threadIdx.x) >> 5;
    int lane = threadIdx.x & 31;
    if (w >= ROWS_) return;
    const float* r = in + (size_t)w * C_;
    float4 a = *(const float4*)(r + lane * 4);
    float4 b = *(const float4*)(r + 128 + lane * 4);
    float s = a.x + a.y + a.z + a.w + b.x + b.y + b.z + b.w;
    float q = a.x*a.x + a.y*a.y + a.z*a.z + a.w*a.w
            + b.x*b.x + b.y*b.y + b.z*b.z + b.w*b.w;
    #pragma unroll
    for (int o = 16; o; o >>= 1) {
        s += __shfl_xor_sync(0xffffffffu, s, o);
        q += __shfl_xor_sync(0xffffffffu, q, o);
    }
    float mean = s * (1.0f / C_);
    float inv = rsqrtf(q * (1.0f / C_) - mean * mean + 1e-5f);
    float4 g0 = *(const float4*)(g + lane * 4);
    float4 g1 = *(const float4*)(g + 128 + lane * 4);
    float4 b0 = *(const float4*)(bt + lane * 4);
    float4 b1 = *(const float4*)(bt + 128 + lane * 4);
    float4 o0, o1;
    o0.x = (a.x - mean) * inv * g0.x + b0.x;
    o0.y = (a.y - mean) * inv * g0.y + b0.y;
    o0.z = (a.z - mean) * inv * g0.z + b0.z;
    o0.w = (a.w - mean) * inv * g0.w + b0.w;
    o1.x = (b.x - mean) * inv * g1.x + b1.x;
    o1.y = (b.y - mean) * inv * g1.y + b1.y;
    o1.z = (b.z - mean) * inv * g1.z + b1.z;
    o1.w = (b.w - mean) * inv * g1.w + b1.w;
    OutT* po = out + (size_t)w * C_;
    store8(po + lane * 4, o0);
    store8(po + 128 + lane * 4, o1);
}

// --------- fused: dwconv3(xn) -> LN -> gelu -> +xn -> bf16 out --------------
// one block per token, one thread per channel
__global__ __launch_bounds__(256)
void sr_fuse(const float* __restrict__ xn, __nv_bfloat16* __restrict__ out,
             const float* __restrict__ sw, const float* __restrict__ sb,
             const float* __restrict__ ag, const float* __restrict__ ab)
{
    __shared__ float red[16];
    int n = blockIdx.x;
    int b = n >> 12, pos = n & 4095;
    int h = pos >> 6, w = pos & 63;
    int c = threadIdx.x;
    float acc = sb[c];
    #pragma unroll
    for (int dy = -1; dy <= 1; dy++) {
        int hh = h + dy;
        if ((unsigned)hh >= 64u) continue;
        #pragma unroll
        for (int dx = -1; dx <= 1; dx++) {
            int ww = w + dx;
            if ((unsigned)ww >= 64u) continue;
            int k = (dy + 1) * 3 + (dx + 1);
            acc += xn[((size_t)(b * N_ + (hh << 6) + ww)) * C_ + c] * sw[c * 9 + k];
        }
    }
    // block LN over 256 values
    float s = acc, q = acc * acc;
    #pragma unroll
    for (int o = 16; o; o >>= 1) {
        s += __shfl_xor_sync(0xffffffffu, s, o);
        q += __shfl_xor_sync(0xffffffffu, q, o);
    }
    int wid = c >> 5, lane = c & 31;
    if (lane == 0) { red[wid] = s; red[8 + wid] = q; }
    __syncthreads();
    if (wid == 0) {
        float ss = (lane < 8) ? red[lane] : 0.0f;
        float qq = (lane < 8) ? red[8 + lane] : 0.0f;
        #pragma unroll
        for (int o = 4; o; o >>= 1) {
            ss += __shfl_xor_sync(0xffffffffu, ss, o);
            qq += __shfl_xor_sync(0xffffffffu, qq, o);
        }
        if (lane == 0) { red[0] = ss; red[1] = qq; }
    }
    __syncthreads();
    float mean = red[0] * (1.0f / C_);
    float inv = rsqrtf(red[1] * (1.0f / C_) - mean * mean + 1e-5f);
    float v = (acc - mean) * inv * ag[c] + ab[c];
    float xa = xn[(size_t)n * C_ + c] + geluf(v);
    out[(size_t)n * C_ + c] = __float2bfloat16_rn(xa);
}

// ---------------- depthwise 3x3 bf16 in/out + gelu (HID=1024 path) ----------
__global__ void dwconv3_bf16(const __nv_bfloat16* __restrict__ in,
                             __nv_bfloat16* __restrict__ out,
                             const float* __restrict__ w, const float* __restrict__ bias)
{
    const int CH = HID_, C4 = CH / 4;
    int idx = blockIdx.x * blockDim.x + threadIdx.x;
    if (idx >= B_ * N_ * C4) return;
    int c4 = idx % C4;
    int n  = (idx / C4) % N_;
    int b  = idx / (C4 * N_);
    int h = n >> 6, wp = n & 63;
    int c0 = c4 * 4;
    float wr[4][9];
    #pragma unroll
    for (int i = 0; i < 4; i++)
        #pragma unroll
        for (int k = 0; k < 9; k++)
            wr[i][k] = w[(c0 + i) * 9 + k];
    float a0 = bias[c0], a1 = bias[c0 + 1], a2 = bias[c0 + 2], a3 = bias[c0 + 3];
    #pragma unroll
    for (int dy = -1; dy <= 1; dy++) {
        int hh = h + dy;
        if ((unsigned)hh >= 64u) continue;
        #pragma unroll
        for (int dx = -1; dx <= 1; dx++) {
            int ww = wp + dx;
            if ((unsigned)ww >= 64u) continue;
            int k = (dy + 1) * 3 + (dx + 1);
            uint2 raw = *(const uint2*)(in + ((size_t)(b * N_ + hh * 64 + ww)) * CH + c0);
            float2 f0 = __bfloat1622float2(*reinterpret_cast<__nv_bfloat162*>(&raw.x));
            float2 f1 = __bfloat1622float2(*reinterpret_cast<__nv_bfloat162*>(&raw.y));
            a0 += f0.x * wr[0][k];
            a1 += f0.y * wr[1][k];
            a2 += f1.x * wr[2][k];
            a3 += f1.y * wr[3][k];
        }
    }
    float4 o = make_float4(geluf(a0), geluf(a1), geluf(a2), geluf(a3));
    store8(out + ((size_t)(b * N_ + n)) * CH + c0, o);
}

// ---------------- BF16 tensor-core GEMM: C = A[M,K] @ W[N,K]^T --------------
#define HSTR  72                  // halves per smem row (64 + 8 pad)
#define HTILE (128 * HSTR)

__device__ __forceinline__ void cp16(uint32_t d, const void* s) {
    asm volatile("cp.async.cg.shared.global [%0], [%1], 16;" :: "r"(d), "l"(s));
}

template <typename OutT>
__global__ __launch_bounds__(256, 2)
void gemm_bf16(const __nv_bfloat16* __restrict__ A, const __nv_bfloat16* __restrict__ W,
               OutT* __restrict__ Cout, int M, int N, int K,
               const float* __restrict__ bias,
               const float* __restrict__ r1, const float* __restrict__ r2)
{
    extern __shared__ __nv_bfloat16 sh16[];
    __nv_bfloat16* Ash = sh16;
    __nv_bfloat16* Bsh = sh16 + 2 * HTILE;

    int tid = threadIdx.x;
    int warp = tid >> 5, lane = tid & 31;
    int wm = warp >> 2, wn = warp & 3;
    int bm = blockIdx.y * 128, bn = blockIdx.x * 128;
    int gr = lane >> 2, gc = lane & 3;

    float acc[4][4][4];
    #pragma unroll
    for (int i = 0; i < 4; i++)
        #pragma unroll
        for (int j = 0; j < 4; j++)
            #pragma unroll
            for (int q = 0; q < 4; q++) acc[i][j][q] = 0.0f;

    int KT = K >> 6;

    int ldr = tid >> 3;
    int ldc = (tid & 7) * 8;
    const __nv_bfloat16* Abase = A + (size_t)(bm + ldr) * K + ldc;
    const __nv_bfloat16* Wbase = W + (size_t)(bn + ldr) * K + ldc;
    uint32_t sAd = (uint32_t)__cvta_generic_to_shared(&Ash[ldr * HSTR + ldc]);
    uint32_t sBd = (uint32_t)__cvta_generic_to_shared(&Bsh[ldr * HSTR + ldc]);
    const uint32_t stageB = HTILE * 2;
    const uint32_t rowB   = 32 * HSTR * 2;

    #define LOAD_STAGE(st, kb) do {                                            \
        uint32_t so = (st) * stageB;                                           \
        size_t go = (size_t)(kb) * 64;                                         \
        _Pragma("unroll")                                                      \
        for (int it = 0; it < 4; it++) {                                       \
            cp16(sAd + so + it * rowB, Abase + (size_t)(it * 32) * K + go);    \
            cp16(sBd + so + it * rowB, Wbase + (size_t)(it * 32) * K + go);    \
        }                                                                      \
        asm volatile("cp.async.commit_group;");                                \
    } while (0)

    LOAD_STAGE(0, 0);
    int st = 0;
    for (int kb = 0; kb < KT; kb++) {
        if (kb + 1 < KT) {
            LOAD_STAGE(st ^ 1, kb + 1);
            asm volatile("cp.async.wait_group 1;");
        } else {
            asm volatile("cp.async.wait_group 0;");
        }
        __syncthreads();

        const uint32_t* As32 = reinterpret_cast<const uint32_t*>(Ash + st * HTILE);
        const uint32_t* Bs32 = reinterpret_cast<const uint32_t*>(Bsh + st * HTILE);
        #pragma unroll
        for (int ks = 0; ks < 4; ks++) {
            uint32_t a[4][4], b[4][2];
            #pragma unroll
            for (int i = 0; i < 4; i++) {
                int base = (wm * 64 + i * 16 + gr) * (HSTR / 2) + ks * 8 + gc;
                a[i][0] = As32[base];
                a[i][1] = As32[base + 8 * (HSTR / 2)];
                a[i][2] = As32[base + 4];
                a[i][3] = As32[base + 8 * (HSTR / 2) + 4];
            }
            #pragma unroll
            for (int j = 0; j < 4; j++) {
                int base = (wn * 32 + j * 8 + gr) * (HSTR / 2) + ks * 8 + gc;
                b[j][0] = Bs32[base];
                b[j][1] = Bs32[base + 4];
            }
            #pragma unroll
            for (int i = 0; i < 4; i++)
                #pragma unroll
                for (int j = 0; j < 4; j++)
                    asm volatile(
                        "mma.sync.aligned.m16n8k16.row.col.f32.bf16.bf16.f32 "
                        "{%0,%1,%2,%3}, {%4,%5,%6,%7}, {%8,%9}, {%0,%1,%2,%3};"
                        : "+f"(acc[i][j][0]), "+f"(acc[i][j][1]),
                          "+f"(acc[i][j][2]), "+f"(acc[i][j][3])
                        : "r"(a[i][0]), "r"(a[i][1]), "r"(a[i][2]), "r"(a[i][3]),
                          "r"(b[j][0]), "r"(b[j][1]));
        }
        __syncthreads();
        st ^= 1;
    }

    #pragma unroll
    for (int i = 0; i < 4; i++) {
        int row0 = bm + wm * 64 + i * 16 + gr;
        #pragma unroll
        for (int j = 0; j < 4; j++) {
            int col = bn + wn * 32 + j * 8 + gc * 2;
            float bx = 0.f, by = 0.f;
            if (bias) { bx = bias[col]; by = bias[col + 1]; }
            size_t o0 = (size_t)row0 * N + col;
            size_t o1 = (size_t)(row0 + 8) * N + col;
            float v0 = acc[i][j][0] + bx, v1 = acc[i][j][1] + by;
            float v2 = acc[i][j][2] + bx, v3 = acc[i][j][3] + by;
            if (r1) {
                float2 p0 = *(const float2*)(r1 + o0);
                float2 p1 = *(const float2*)(r1 + o1);
                v0 += p0.x; v1 += p0.y; v2 += p1.x; v3 += p1.y;
            }
            if (r2) {
                float2 p0 = *(const float2*)(r2 + o0);
                float2 p1 = *(const float2*)(r2 + o1);
                v0 += p0.x; v1 += p0.y; v2 += p1.x; v3 += p1.y;
            }
            if constexpr (sizeof(OutT) == 4) {
                *(float2*)((float*)Cout + o0) = make_float2(v0, v1);
                *(float2*)((float*)Cout + o1) = make_float2(v2, v3);
            } else {
                __nv_bfloat162 h0 = __floats2bfloat162_rn(v0, v1);
                __nv_bfloat162 h1 = __floats2bfloat162_rn(v2, v3);
                *(uint32_t*)((__nv_bfloat16*)Cout + o0) = *reinterpret_cast<uint32_t*>(&h0);
                *(uint32_t*)((__nv_bfloat16*)Cout + o1) = *reinterpret_cast<uint32_t*>(&h1);
            }
        }
    }
}

// ---------------- q softmax over tokens: per-(b,c) online partials ----------
__global__ void qsoft_part(const __nv_bfloat16* __restrict__ qkv)
{
    int b = blockIdx.x, ch = blockIdx.y, c = threadIdx.x;
    const __nv_bfloat16* p = qkv + ((size_t)(b * N_ + ch * 256)) * (3 * C_) + c;
    float m = -1e30f, s = 0.0f;
    for (int i = 0; i < 256; i++) {
        float v = __bfloat162float(p[(size_t)i * (3 * C_)]);
        float nm = fmaxf(m, v);
        s = s * __expf(m - nm) + __expf(v - nm);
        m = nm;
    }
    g_pm[(b * 16 + ch) * C_ + c] = m;
    g_ps[(b * 16 + ch) * C_ + c] = s;
}

__global__ void qsoft_comb()
{
    int idx = blockIdx.x * blockDim.x + threadIdx.x;
    if (idx >= B_ * C_) return;
    int b = idx >> 8, c = idx & 255;
    float M = -1e30f;
    for (int ch = 0; ch < 16; ch++) M = fmaxf(M, g_pm[(b * 16 + ch) * C_ + c]);
    float S = 0.0f;
    for (int ch = 0; ch < 16; ch++)
        S += g_ps[(b * 16 + ch) * C_ + c] * __expf(g_pm[(b * 16 + ch) * C_ + c] - M);
    g_cmax[idx] = M;
    g_cinv[idx] = 1.0f / S;
}

// ---------------- ctx = softmax_d(k)^T @ v ----------------------------------
__global__ __launch_bounds__(256) void ctx_kernel(const __nv_bfloat16* __restrict__ qkv)
{
    int chunk = blockIdx.x;
    int head  = blockIdx.y;
    int b     = blockIdx.z;
    __shared__ float ks[32][33];
    __shared__ float vs[32][33];
    int tid = threadIdx.x, lane = tid & 31, wp = tid >> 5;
    float acc[4] = {0.f, 0.f, 0.f, 0.f};
    for (int it = 0; it < 8; it++) {
        int nb = chunk * 256 + it * 32;
        #pragma unroll
        for (int j = 0; j < 8; j++) {
            int id = tid + 256 * j;
            int r = id >> 6, inner = id & 63;
            const __nv_bfloat16* src =
                qkv + ((size_t)(b * N_ + nb + r)) * (3 * C_) + C_ + head * D_;
            if (inner < 32) ks[r][inner] = __bfloat162float(src[inner]);
            else            vs[r][inner - 32] = __bfloat162float(src[C_ + inner - 32]);
        }
        __syncthreads();
        #pragma unroll
        for (int rr = 0; rr < 4; rr++) {
            int r = wp * 4 + rr;
            float v = ks[r][lane];
            float mx = v;
            #pragma unroll
            for (int o = 16; o; o >>= 1) mx = fmaxf(mx, __shfl_xor_sync(0xffffffffu, mx, o));
            float e = __expf(v - mx);
            float su = e;
            #pragma unroll
            for (int o = 16; o; o >>= 1) su += __shfl_xor_sync(0xffffffffu, su, o);
            ks[r][lane] = e / su;
        }
        __syncthreads();
        #pragma unroll
        for (int r = 0; r < 32; r++) {
            float vv = vs[r][lane];
            #pragma unroll
            for (int i = 0; i < 4; i++) acc[i] += ks[r][wp + 8 * i] * vv;
        }
        __syncthreads();
    }
    #pragma unroll
    for (int i = 0; i < 4; i++) {
        int e = wp + 8 * i;
        g_ctxp[(size_t)chunk * (B_ * HEADS_ * D_ * D_) +
               ((b * HEADS_ + head) * D_ + e) * D_ + lane] = acc[i];
    }
}

__global__ void ctx_comb()
{
    int idx = blockIdx.x * blockDim.x + threadIdx.x;
    if (idx >= B_ * HEADS_ * D_ * D_) return;
    float s = 0.0f;
    for (int ch = 0; ch < 16; ch++) s += g_ctxp[(size_t)ch * (B_ * HEADS_ * D_ * D_) + idx];
    g_ctx[idx] = s;
}

// ---------------- attn = softmax_N(q) @ ctx  (warp per head, ctx in regs) ---
__global__ __launch_bounds__(256) void attn2(const __nv_bfloat16* __restrict__ qkv,
                                             __nv_bfloat16* __restrict__ out)
{
    int b = blockIdx.y;
    int base = blockIdx.x * 128;            // 128 tokens per block
    int h = threadIdx.x >> 5;               // warp = head
    int lane = threadIdx.x & 31;
    int ch = h * 32 + lane;

    float cm = g_cmax[b * C_ + ch];
    float ci = g_cinv[b * C_ + ch];
    float ctxr[32];
    #pragma unroll
    for (int e = 0; e < 32; e++)
        ctxr[e] = g_ctx[((b * HEADS_ + h) * D_ + e) * D_ + lane];

    const __nv_bfloat16* qbase = qkv + (size_t)(b * N_ + base) * (3 * C_) + ch;
    __nv_bfloat16* obase = out + (size_t)(b * N_ + base) * C_ + ch;
    for (int t = 0; t < 128; t++) {
        float q = __bfloat162float(qbase[(size_t)t * (3 * C_)]);
        float p = __expf(q - cm) * ci;
        float acc = 0.0f;
        #pragma unroll
        for (int e = 0; e < 32; e++)
            acc += __shfl_sync(0xffffffffu, p, e) * ctxr[e];
        obase[(size_t)t * C_] = __float2bfloat16_rn(acc);
    }
}

// ---------------- CSDA ------------------------------------------------------
__global__ void cpool_part(const float* __restrict__ x3)
{
    int b = blockIdx.x, ch = blockIdx.y, c = threadIdx.x;
    const float* p = x3 + ((size_t)(b * N_ + ch * 128)) * C_ + c;
    float s = 0.0f, m = -1e30f;
    for (int i = 0; i < 128; i++) {
        float v = p[(size_t)i * C_];
        s += v; m = fmaxf(m, v);
    }
    g_cps[(b * 32 + ch) * C_ + c] = s;
    g_cpm[(b * 32 + ch) * C_ + c] = m;
}

__global__ void cpool_comb()
{
    int idx = blockIdx.x * blockDim.x + threadIdx.x;
    if (idx >= B_ * C_) return;
    int b = idx >> 8, c = idx & 255;
    float s = 0.0f, m = -1e30f;
    for (int ch = 0; ch < 32; ch++) {
        s += g_cps[(b * 32 + ch) * C_ + c];
        m = fmaxf(m, g_cpm[(b * 32 + ch) * C_ + c]);
    }
    g_avg[idx] = s * (1.0f / N_);
    g_mx[idx] = m;
}

__global__ void ca_mlp(const float* __restrict__ w1, const float* __restrict__ w2)
{
    int b = blockIdx.x, t = threadIdx.x;
    __shared__ float hsum[16];
    if (t < 16) {
        float sa = 0.0f, sm = 0.0f;
        for (int c = 0; c < C_; c++) {
            float w = w1[t * C_ + c];
            sa += g_avg[b * C_ + c] * w;
            sm += g_mx[b * C_ + c] * w;
        }
        hsum[t] = fmaxf(sa, 0.0f) + fmaxf(sm, 0.0f);
    }
    __syncthreads();
    float acc = 0.0f;
    #pragma unroll
    for (int j = 0; j < 16; j++) acc += w2[t * 16 + j] * hsum[j];
    g_ca[b * C_ + t] = sigmf(acc);
}

__global__ void spool(const float* __restrict__ x3)
{
    int w = (blockIdx.x * blockDim.x + threadIdx.x) >> 5;
    int lane = threadIdx.x & 31;
    if (w >= ROWS_) return;
    int b = w >> 12;
    const float* r = x3 + (size_t)w * C_;
    const float* ca = g_ca + b * C_;
    float4 a = *(const float4*)(r + lane * 4);
    float4 c0 = *(const float4*)(ca + lane * 4);
    float4 bvals = *(const float4*)(r + 128 + lane * 4);
    float4 c1 = *(const float4*)(ca + 128 + lane * 4);
    float v0 = a.x * c0.x, v1 = a.y * c0.y, v2 = a.z * c0.z, v3 = a.w * c0.w;
    float v4 = bvals.x * c1.x, v5 = bvals.y * c1.y, v6 = bvals.z * c1.z, v7 = bvals.w * c1.w;
    float s = v0 + v1 + v2 + v3 + v4 + v5 + v6 + v7;
    float m = fmaxf(fmaxf(fmaxf(v0, v1), fmaxf(v2, v3)), fmaxf(fmaxf(v4, v5), fmaxf(v6, v7)));
    #pragma unroll
    for (int o = 16; o; o >>= 1) {
        s += __shfl_xor_sync(0xffffffffu, s, o);
        m = fmaxf(m, __shfl_xor_sync(0xffffffffu, m, o));
    }
    if (lane == 0) {
        g_sm[w] = s * (1.0f / C_);
        g_sx[w] = m;
    }
}

__global__ void conv7(const float* __restrict__ spw, const float* __restrict__ spb)
{
    int idx = blockIdx.x * blockDim.x + threadIdx.x;
    if (idx >= ROWS_) return;
    int b = idx >> 12, n = idx & 4095;
    int h = n >> 6, w = n & 63;
    float acc = spb[0];
    #pragma unroll
    for (int ch = 0; ch < 2; ch++) {
        const float* src = ch ? g_sx : g_sm;
        const float* wp = spw + ch * 49;
        for (int ky = 0; ky < 7; ky++) {
            int y = h + ky - 3;
            if ((unsigned)y >= 64u) continue;
            for (int kx = 0; kx < 7; kx++) {
                int x = w + kx - 3;
                if ((unsigned)x >= 64u) continue;
                acc += src[(b << 12) + (y << 6) + x] * wp[ky * 7 + kx];
            }
        }
    }
    g_sa[idx] = sigmf(acc);
}

__global__ void final_scale(const float* __restrict__ x3, float* __restrict__ out)
{
    int idx = blockIdx.x * blockDim.x + threadIdx.x;
    if (idx >= ROWS_ * 64) return;
    int c4 = idx & 63;
    int row = idx >> 6;
    int b = row >> 12;
    float4 v = *(const float4*)(x3 + (size_t)row * C_ + c4 * 4);
    float4 ca = *(const float4*)(g_ca + b * C_ + c4 * 4);
    float sa = g_sa[row];
    v.x *= ca.x * sa; v.y *= ca.y * sa; v.z *= ca.z * sa; v.w *= ca.w * sa;
    *(float4*)(out + (size_t)row * C_ + c4 * 4) = v;
}

// ---------------------------------------------------------------------------
extern "C" void kernel_launch(void* const* d_in, const int* in_sizes, int n_in,
                              void* d_out, int out_size)
{
    int p = (n_in >= 24 && in_sizes[1] == 1 && in_sizes[2] == 1) ? 3 : 1;
    const float* x      = (const float*)d_in[0];
    const float* n1_g   = (const float*)d_in[p + 0];
    const float* n1_b   = (const float*)d_in[p + 1];
    const float* sr_w   = (const float*)d_in[p + 2];
    const float* sr_b   = (const float*)d_in[p + 3];
    const float* an_g   = (const float*)d_in[p + 4];
    const float* an_b   = (const float*)d_in[p + 5];
    const float* qkv_w  = (const float*)d_in[p + 6];
    const float* proj_w = (const float*)d_in[p + 7];
    const float* proj_b = (const float*)d_in[p + 8];
    const float* n2_g   = (const float*)d_in[p + 9];
    const float* n2_b   = (const float*)d_in[p + 10];
    const float* fc1_w  = (const float*)d_in[p + 11];
    const float* fc1_b  = (const float*)d_in[p + 12];
    const float* dw_w   = (const float*)d_in[p + 13];
    const float* dw_b   = (const float*)d_in[p + 14];
    const float* fc2_w  = (const float*)d_in[p + 15];
    const float* fc2_b  = (const float*)d_in[p + 16];
    const float* ca_w1  = (const float*)d_in[p + 17];
    const float* ca_w2  = (const float*)d_in[p + 18];
    const float* sp_w   = (const float*)d_in[p + 19];
    const float* sp_b   = (const float*)d_in[p + 20];
    float* out = (float*)d_out;

    float *pxn, *pb1, *pb2;
    __nv_bfloat16 *pqkv16, *pa16, *ph16a, *ph16b, *pw16;
    cudaGetSymbolAddress((void**)&pxn,    g_xn);
    cudaGetSymbolAddress((void**)&pb1,    g_b1);
    cudaGetSymbolAddress((void**)&pb2,    g_b2);
    cudaGetSymbolAddress((void**)&pqkv16, g_qkv16);
    cudaGetSymbolAddress((void**)&pa16,   g_a16);
    cudaGetSymbolAddress((void**)&ph16a,  g_h16a);
    cudaGetSymbolAddress((void**)&ph16b,  g_h16b);
    cudaGetSymbolAddress((void**)&pw16,   g_w16);

    const int TPB = 256;
    const int GEMM_SMEM = 4 * HTILE * 2;   // 73728 bytes
    cudaFuncSetAttribute(gemm_bf16<float>, cudaFuncAttributeMaxDynamicSharedMemorySize,
                         GEMM_SMEM);
    cudaFuncSetAttribute(gemm_bf16<__nv_bfloat16>, cudaFuncAttributeMaxDynamicSharedMemorySize,
                         GEMM_SMEM);

    // 0. bf16 weight conversion
    f2bf<<<(196608 / 2 + TPB - 1) / TPB, TPB>>>(qkv_w,  pw16 + W16_QKV,  196608);
    f2bf<<<(65536  / 2 + TPB - 1) / TPB, TPB>>>(proj_w, pw16 + W16_PROJ, 65536);
    f2bf<<<(262144 / 2 + TPB - 1) / TPB, TPB>>>(fc1_w,  pw16 + W16_FC1,  262144);
    f2bf<<<(262144 / 2 + TPB - 1) / TPB, TPB>>>(fc2_w,  pw16 + W16_FC2,  262144);

    // 1. xn = LN1(x)
    ln256<float><<<ROWS_ * 32 / TPB, TPB>>>(x, pxn, n1_g, n1_b);
    // 2+3. xa16 = bf16(xn + gelu(LN_act(dwconv3(xn))))  (fused)
    sr_fuse<<<ROWS_, TPB>>>(pxn, pa16, sr_w, sr_b, an_g, an_b);
    // 4. qkv = xa @ qkv_w^T  (bf16 out)
    {
        dim3 g(3 * C_ / 128, ROWS_ / 128);
        gemm_bf16<__nv_bfloat16><<<g, TPB, GEMM_SMEM>>>(pa16, pw16 + W16_QKV, pqkv16,
                                                        ROWS_, 3 * C_, C_, nullptr, nullptr, nullptr);
    }
    // 5. q column-softmax stats
    {
        dim3 g(B_, 16);
        qsoft_part<<<g, TPB>>>(pqkv16);
        qsoft_comb<<<(B_ * C_ + TPB - 1) / TPB, TPB>>>();
    }
    // 6. ctx = softmax_d(k)^T v
    {
        dim3 g(16, HEADS_, B_);
        ctx_kernel<<<g, TPB>>>(pqkv16);
        ctx_comb<<<(B_ * HEADS_ * D_ * D_ + TPB - 1) / TPB, TPB>>>();
    }
    // 7. attn = softmax_N(q) @ ctx -> a16 (bf16)
    {
        dim3 g(N_ / 128, B_);
        attn2<<<g, TPB>>>(pqkv16, pa16);
    }
    // 8. x2 = x + attn @ proj_w^T + proj_b + xn -> b1
    {
        dim3 g(C_ / 128, ROWS_ / 128);
        gemm_bf16<float><<<g, TPB, GEMM_SMEM>>>(pa16, pw16 + W16_PROJ, pb1,
                                                ROWS_, C_, C_, proj_b, x, pxn);
    }
    // 9. ln2(x2) -> a16 (bf16)
    ln256<__nv_bfloat16><<<ROWS_ * 32 / TPB, TPB>>>(pb1, pa16, n2_g, n2_b);
    // 10. fc1 -> h16a (bf16)
    {
        dim3 g(HID_ / 128, ROWS_ / 128);
        gemm_bf16<__nv_bfloat16><<<g, TPB, GEMM_SMEM>>>(pa16, pw16 + W16_FC1, ph16a,
                                                        ROWS_, HID_, C_, fc1_b, nullptr, nullptr);
    }
    // 11. dwconv + gelu (bf16) -> h16b
    dwconv3_bf16<<<(B_ * N_ * (HID_ / 4) + TPB - 1) / TPB, TPB>>>(ph16a, ph16b, dw_w, dw_b);
    // 12. x3 = x2 + gelu_dw @ fc2_w^T + fc2_b -> b2
    {
        dim3 g(C_ / 128, ROWS_ / 128);
        gemm_bf16<float><<<g, TPB, GEMM_SMEM>>>(ph16b, pw16 + W16_FC2, pb2,
                                                ROWS_, C_, HID_, fc2_b, pb1, nullptr);
    }
    // 13. channel pools
    {
        dim3 g(B_, 32);
        cpool_part<<<g, TPB>>>(pb2);
        cpool_comb<<<(B_ * C_ + TPB - 1) / TPB, TPB>>>();
    }
    // 14. channel attention MLP
    ca_mlp<<<B_, TPB>>>(ca_w1, ca_w2);
    // 15. spatial pools of x3*ca
    spool<<<ROWS_ * 32 / TPB, TPB>>>(pb2);
    // 16. 7x7 spatial conv -> sa
    conv7<<<(ROWS_ + TPB - 1) / TPB, TPB>>>(sp_w, sp_b);
    // 17. out = x3 * ca * sa
    final_scale<<<(ROWS_ * 64 + TPB - 1) / TPB, TPB>>>(pb2, out);
}

// round 6
// speedup vs baseline: 4.2584x; 1.4623x over previous
#include <cuda_runtime.h>
#include <cuda_bf16.h>
#include <math.h>
#include <stdint.h>

// Problem constants
#define B_    16
#define N_    4096
#define C_    256
#define HEADS_ 8
#define D_    32
#define HID_  1024
#define ROWS_ 65536          // B_*N_

// ---------------- scratch (device globals; no allocation allowed) ----------
__device__ float g_xn  [ROWS_ * C_];           // norm1(x)
__device__ float g_b1  [ROWS_ * C_];           // x2
__device__ float g_b2  [ROWS_ * C_];           // x3
__device__ __nv_bfloat16 g_qkv16[ROWS_ * 3 * C_]; // qkv (bf16)
__device__ __nv_bfloat16 g_a16 [ROWS_ * C_];   // xa / attn / ln2 (bf16, reused)
__device__ __nv_bfloat16 g_h16a[ROWS_ * HID_]; // fc1 out (bf16)
__device__ __nv_bfloat16 g_h16b[ROWS_ * HID_]; // dwconv+gelu out (bf16)
__device__ __nv_bfloat16 g_w16 [786432];       // bf16 weights (qkv|proj|fc1|fc2)
#define W16_QKV  0
#define W16_PROJ 196608
#define W16_FC1  262144
#define W16_FC2  524288
__device__ float g_pm  [B_ * 16 * C_];
__device__ float g_ps  [B_ * 16 * C_];
__device__ float g_cmax[B_ * C_];
__device__ float g_cinv[B_ * C_];
__device__ float g_ctxp[16 * B_ * HEADS_ * D_ * D_];
__device__ float g_ctx [B_ * HEADS_ * D_ * D_];
__device__ float g_cps [B_ * 32 * C_];
__device__ float g_cpm [B_ * 32 * C_];
__device__ float g_avg [B_ * C_];
__device__ float g_mx  [B_ * C_];
__device__ float g_ca  [B_ * C_];
__device__ float g_sm  [ROWS_];
__device__ float g_sx  [ROWS_];
__device__ float g_sa  [ROWS_];

__device__ __forceinline__ float geluf(float x) {
    return 0.5f * x * (1.0f + erff(x * 0.70710678118654752440f));
}
__device__ __forceinline__ float sigmf(float x) {
    return 1.0f / (1.0f + __expf(-x));
}
__device__ __forceinline__ void store8(float* p, float4 v) { *(float4*)p = v; }
__device__ __forceinline__ void store8(__nv_bfloat16* p, float4 v) {
    __nv_bfloat162 h0 = __floats2bfloat162_rn(v.x, v.y);
    __nv_bfloat162 h1 = __floats2bfloat162_rn(v.z, v.w);
    uint2 u;
    u.x = *reinterpret_cast<uint32_t*>(&h0);
    u.y = *reinterpret_cast<uint32_t*>(&h1);
    *(uint2*)p = u;
}

// ---------------- fp32 -> bf16 weight conversion (all 4 weights, 1 kernel) --
__global__ void f2bf_all(const float* __restrict__ s0, const float* __restrict__ s1,
                         const float* __restrict__ s2, const float* __restrict__ s3,
                         __nv_bfloat16* __restrict__ dst)
{
    int i = blockIdx.x * blockDim.x + threadIdx.x;   // pairs; total 786432/2
    if (i >= 393216) return;
    int e = i * 2;
    const float* src;
    int off;
    if (e < W16_PROJ)      { src = s0; off = e; }
    else if (e < W16_FC1)  { src = s1; off = e - W16_PROJ; }
    else if (e < W16_FC2)  { src = s2; off = e - W16_FC1; }
    else                   { src = s3; off = e - W16_FC2; }
    float2 v = *(const float2*)(src + off);
    __nv_bfloat162 h = __floats2bfloat162_rn(v.x, v.y);
    *(uint32_t*)(dst + e) = *reinterpret_cast<uint32_t*>(&h);
}

// ---------------- LayerNorm (256 wide), one warp per row --------------------
template <typename OutT>
__global__ void ln256(const float* __restrict__ in, OutT* __restrict__ out,
                      const float* __restrict__ g, const float* __restrict__ bt)
{
    int w = (blockIdx.x * blockDim.x + threadIdx.x) >> 5;
    int lane = threadIdx.x & 31;
    if (w >= ROWS_) return;
    const float* r = in + (size_t)w * C_;
    float4 a = *(const float4*)(r + lane * 4);
    float4 b = *(const float4*)(r + 128 + lane * 4);
    float s = a.x + a.y + a.z + a.w + b.x + b.y + b.z + b.w;
    float q = a.x*a.x + a.y*a.y + a.z*a.z + a.w*a.w
            + b.x*b.x + b.y*b.y + b.z*b.z + b.w*b.w;
    #pragma unroll
    for (int o = 16; o; o >>= 1) {
        s += __shfl_xor_sync(0xffffffffu, s, o);
        q += __shfl_xor_sync(0xffffffffu, q, o);
    }
    float mean = s * (1.0f / C_);
    float inv = rsqrtf(q * (1.0f / C_) - mean * mean + 1e-5f);
    float4 g0 = *(const float4*)(g + lane * 4);
    float4 g1 = *(const float4*)(g + 128 + lane * 4);
    float4 b0 = *(const float4*)(bt + lane * 4);
    float4 b1 = *(const float4*)(bt + 128 + lane * 4);
    float4 o0, o1;
    o0.x = (a.x - mean) * inv * g0.x + b0.x;
    o0.y = (a.y - mean) * inv * g0.y + b0.y;
    o0.z = (a.z - mean) * inv * g0.z + b0.z;
    o0.w = (a.w - mean) * inv * g0.w + b0.w;
    o1.x = (b.x - mean) * inv * g1.x + b1.x;
    o1.y = (b.y - mean) * inv * g1.y + b1.y;
    o1.z = (b.z - mean) * inv * g1.z + b1.z;
    o1.w = (b.w - mean) * inv * g1.w + b1.w;
    OutT* po = out + (size_t)w * C_;
    store8(po + lane * 4, o0);
    store8(po + 128 + lane * 4, o1);
}

// --------- fused: dwconv3(xn) -> LN -> gelu -> +xn -> bf16 out --------------
__global__ __launch_bounds__(256)
void sr_fuse(const float* __restrict__ xn, __nv_bfloat16* __restrict__ out,
             const float* __restrict__ sw, const float* __restrict__ sb,
             const float* __restrict__ ag, const float* __restrict__ ab)
{
    __shared__ float red[16];
    int n = blockIdx.x;
    int b = n >> 12, pos = n & 4095;
    int h = pos >> 6, w = pos & 63;
    int c = threadIdx.x;
    float acc = sb[c];
    #pragma unroll
    for (int dy = -1; dy <= 1; dy++) {
        int hh = h + dy;
        if ((unsigned)hh >= 64u) continue;
        #pragma unroll
        for (int dx = -1; dx <= 1; dx++) {
            int ww = w + dx;
            if ((unsigned)ww >= 64u) continue;
            int k = (dy + 1) * 3 + (dx + 1);
            acc += xn[((size_t)(b * N_ + (hh << 6) + ww)) * C_ + c] * sw[c * 9 + k];
        }
    }
    float s = acc, q = acc * acc;
    #pragma unroll
    for (int o = 16; o; o >>= 1) {
        s += __shfl_xor_sync(0xffffffffu, s, o);
        q += __shfl_xor_sync(0xffffffffu, q, o);
    }
    int wid = c >> 5, lane = c & 31;
    if (lane == 0) { red[wid] = s; red[8 + wid] = q; }
    __syncthreads();
    if (wid == 0) {
        float ss = (lane < 8) ? red[lane] : 0.0f;
        float qq = (lane < 8) ? red[8 + lane] : 0.0f;
        #pragma unroll
        for (int o = 4; o; o >>= 1) {
            ss += __shfl_xor_sync(0xffffffffu, ss, o);
            qq += __shfl_xor_sync(0xffffffffu, qq, o);
        }
        if (lane == 0) { red[0] = ss; red[1] = qq; }
    }
    __syncthreads();
    float mean = red[0] * (1.0f / C_);
    float inv = rsqrtf(red[1] * (1.0f / C_) - mean * mean + 1e-5f);
    float v = (acc - mean) * inv * ag[c] + ab[c];
    float xa = xn[(size_t)n * C_ + c] + geluf(v);
    out[(size_t)n * C_ + c] = __float2bfloat16_rn(xa);
}

// --------- depthwise 3x3 bf16 + gelu, 4-token sliding window ----------------
// block: 256 thr = 16 wgroups(4 tokens) x 16 c4-subs; grid (C4/16, 64 h, B)
__global__ __launch_bounds__(256)
void dwconv3_bf16_v2(const __nv_bfloat16* __restrict__ in,
                     __nv_bfloat16* __restrict__ out,
                     const float* __restrict__ w, const float* __restrict__ bias)
{
    const int CH = HID_;
    int tid = threadIdx.x;
    int c0 = (blockIdx.x * 16 + (tid & 15)) * 4;
    int h  = blockIdx.y;
    int b  = blockIdx.z;
    int w0 = (tid >> 4) * 4;

    float wr[4][9];
    #pragma unroll
    for (int i = 0; i < 4; i++)
        #pragma unroll
        for (int k = 0; k < 9; k++)
            wr[i][k] = w[(c0 + i) * 9 + k];

    float acc[4][4];
    #pragma unroll
    for (int t = 0; t < 4; t++)
        #pragma unroll
        for (int i = 0; i < 4; i++)
            acc[t][i] = bias[c0 + i];

    #pragma unroll
    for (int dy = -1; dy <= 1; dy++) {
        int hh = h + dy;
        if ((unsigned)hh >= 64u) continue;
        const __nv_bfloat16* rowp = in + ((size_t)(b * N_ + (hh << 6))) * CH + c0;
        #pragma unroll
        for (int wx = -1; wx <= 4; wx++) {
            int ww = w0 + wx;
            if ((unsigned)ww >= 64u) continue;
            uint2 raw = *(const uint2*)(rowp + (size_t)ww * CH);
            float2 f0 = __bfloat1622float2(*reinterpret_cast<__nv_bfloat162*>(&raw.x));
            float2 f1 = __bfloat1622float2(*reinterpret_cast<__nv_bfloat162*>(&raw.y));
            float f[4] = {f0.x, f0.y, f1.x, f1.y};
            #pragma unroll
            for (int t = 0; t < 4; t++) {
                int kx = wx - t;
                if (kx < -1 || kx > 1) continue;
                int k = (dy + 1) * 3 + kx + 1;
                #pragma unroll
                for (int i = 0; i < 4; i++)
                    acc[t][i] += f[i] * wr[i][k];
            }
        }
    }
    #pragma unroll
    for (int t = 0; t < 4; t++) {
        float4 o = make_float4(geluf(acc[t][0]), geluf(acc[t][1]),
                               geluf(acc[t][2]), geluf(acc[t][3]));
        store8(out + ((size_t)(b * N_ + (h << 6) + w0 + t)) * CH + c0, o);
    }
}

// ---------------- BF16 tensor-core GEMM with ldmatrix ------------------------
#define HSTR  72                  // halves per smem row (64 + 8 pad)
#define HTILE (128 * HSTR)

__device__ __forceinline__ void cp16(uint32_t d, const void* s) {
    asm volatile("cp.async.cg.shared.global [%0], [%1], 16;" :: "r"(d), "l"(s));
}

template <typename OutT>
__global__ __launch_bounds__(256, 2)
void gemm_bf16(const __nv_bfloat16* __restrict__ A, const __nv_bfloat16* __restrict__ W,
               OutT* __restrict__ Cout, int M, int N, int K,
               const float* __restrict__ bias,
               const float* __restrict__ r1, const float* __restrict__ r2)
{
    extern __shared__ __nv_bfloat16 sh16[];
    __nv_bfloat16* Ash = sh16;
    __nv_bfloat16* Bsh = sh16 + 2 * HTILE;

    int tid = threadIdx.x;
    int warp = tid >> 5, lane = tid & 31;
    int wm = warp >> 2, wn = warp & 3;
    int bm = blockIdx.y * 128, bn = blockIdx.x * 128;
    int gr = lane >> 2, gc = lane & 3;

    float acc[4][4][4];
    #pragma unroll
    for (int i = 0; i < 4; i++)
        #pragma unroll
        for (int j = 0; j < 4; j++)
            #pragma unroll
            for (int q = 0; q < 4; q++) acc[i][j][q] = 0.0f;

    int KT = K >> 6;

    int ldr = tid >> 3;
    int ldc = (tid & 7) * 8;
    const __nv_bfloat16* Abase = A + (size_t)(bm + ldr) * K + ldc;
    const __nv_bfloat16* Wbase = W + (size_t)(bn + ldr) * K + ldc;
    uint32_t sAd = (uint32_t)__cvta_generic_to_shared(&Ash[ldr * HSTR + ldc]);
    uint32_t sBd = (uint32_t)__cvta_generic_to_shared(&Bsh[ldr * HSTR + ldc]);
    const uint32_t stageB = HTILE * 2;
    const uint32_t rowB   = 32 * HSTR * 2;

    // ldmatrix per-lane half-offsets (within a fragment tile)
    uint32_t aoff = ((lane & 15) * HSTR + (lane >> 4) * 8) * 2;       // bytes
    uint32_t boff = ((lane & 7) * HSTR + ((lane >> 3) & 1) * 8) * 2;  // bytes
    uint32_t sAbase = (uint32_t)__cvta_generic_to_shared(Ash);
    uint32_t sBbase = (uint32_t)__cvta_generic_to_shared(Bsh);

    #define LOAD_STAGE(st, kb) do {                                            \
        uint32_t so = (st) * stageB;                                           \
        size_t go = (size_t)(kb) * 64;                                         \
        _Pragma("unroll")                                                      \
        for (int it = 0; it < 4; it++) {                                       \
            cp16(sAd + so + it * rowB, Abase + (size_t)(it * 32) * K + go);    \
            cp16(sBd + so + it * rowB, Wbase + (size_t)(it * 32) * K + go);    \
        }                                                                      \
        asm volatile("cp.async.commit_group;");                                \
    } while (0)

    LOAD_STAGE(0, 0);
    int st = 0;
    for (int kb = 0; kb < KT; kb++) {
        if (kb + 1 < KT) {
            LOAD_STAGE(st ^ 1, kb + 1);
            asm volatile("cp.async.wait_group 1;");
        } else {
            asm volatile("cp.async.wait_group 0;");
        }
        __syncthreads();

        uint32_t stA = sAbase + st * stageB;
        uint32_t stB = sBbase + st * stageB;
        #pragma unroll
        for (int ks = 0; ks < 4; ks++) {
            uint32_t a[4][4], b[4][2];
            #pragma unroll
            for (int i = 0; i < 4; i++) {
                uint32_t addr = stA + (uint32_t)((wm * 64 + i * 16) * HSTR + ks * 16) * 2 + aoff;
                asm volatile(
                    "ldmatrix.sync.aligned.m8n8.x4.shared.b16 {%0,%1,%2,%3}, [%4];"
                    : "=r"(a[i][0]), "=r"(a[i][1]), "=r"(a[i][2]), "=r"(a[i][3])
                    : "r"(addr));
            }
            #pragma unroll
            for (int j = 0; j < 4; j++) {
                uint32_t addr = stB + (uint32_t)((wn * 32 + j * 8) * HSTR + ks * 16) * 2 + boff;
                asm volatile(
                    "ldmatrix.sync.aligned.m8n8.x2.shared.b16 {%0,%1}, [%2];"
                    : "=r"(b[j][0]), "=r"(b[j][1])
                    : "r"(addr));
            }
            #pragma unroll
            for (int i = 0; i < 4; i++)
                #pragma unroll
                for (int j = 0; j < 4; j++)
                    asm volatile(
                        "mma.sync.aligned.m16n8k16.row.col.f32.bf16.bf16.f32 "
                        "{%0,%1,%2,%3}, {%4,%5,%6,%7}, {%8,%9}, {%0,%1,%2,%3};"
                        : "+f"(acc[i][j][0]), "+f"(acc[i][j][1]),
                          "+f"(acc[i][j][2]), "+f"(acc[i][j][3])
                        : "r"(a[i][0]), "r"(a[i][1]), "r"(a[i][2]), "r"(a[i][3]),
                          "r"(b[j][0]), "r"(b[j][1]));
        }
        __syncthreads();
        st ^= 1;
    }

    #pragma unroll
    for (int i = 0; i < 4; i++) {
        int row0 = bm + wm * 64 + i * 16 + gr;
        #pragma unroll
        for (int j = 0; j < 4; j++) {
            int col = bn + wn * 32 + j * 8 + gc * 2;
            float bx = 0.f, by = 0.f;
            if (bias) { bx = bias[col]; by = bias[col + 1]; }
            size_t o0 = (size_t)row0 * N + col;
            size_t o1 = (size_t)(row0 + 8) * N + col;
            float v0 = acc[i][j][0] + bx, v1 = acc[i][j][1] + by;
            float v2 = acc[i][j][2] + bx, v3 = acc[i][j][3] + by;
            if (r1) {
                float2 p0 = *(const float2*)(r1 + o0);
                float2 p1 = *(const float2*)(r1 + o1);
                v0 += p0.x; v1 += p0.y; v2 += p1.x; v3 += p1.y;
            }
            if (r2) {
                float2 p0 = *(const float2*)(r2 + o0);
                float2 p1 = *(const float2*)(r2 + o1);
                v0 += p0.x; v1 += p0.y; v2 += p1.x; v3 += p1.y;
            }
            if constexpr (sizeof(OutT) == 4) {
                *(float2*)((float*)Cout + o0) = make_float2(v0, v1);
                *(float2*)((float*)Cout + o1) = make_float2(v2, v3);
            } else {
                __nv_bfloat162 h0 = __floats2bfloat162_rn(v0, v1);
                __nv_bfloat162 h1 = __floats2bfloat162_rn(v2, v3);
                *(uint32_t*)((__nv_bfloat16*)Cout + o0) = *reinterpret_cast<uint32_t*>(&h0);
                *(uint32_t*)((__nv_bfloat16*)Cout + o1) = *reinterpret_cast<uint32_t*>(&h1);
            }
        }
    }
}

// ---------------- q softmax over tokens: per-(b,c) online partials ----------
__global__ void qsoft_part(const __nv_bfloat16* __restrict__ qkv)
{
    int b = blockIdx.x, ch = blockIdx.y, c = threadIdx.x;
    const __nv_bfloat16* p = qkv + ((size_t)(b * N_ + ch * 256)) * (3 * C_) + c;
    float m = -1e30f, s = 0.0f;
    for (int i = 0; i < 256; i++) {
        float v = __bfloat162float(p[(size_t)i * (3 * C_)]);
        float nm = fmaxf(m, v);
        s = s * __expf(m - nm) + __expf(v - nm);
        m = nm;
    }
    g_pm[(b * 16 + ch) * C_ + c] = m;
    g_ps[(b * 16 + ch) * C_ + c] = s;
}

__global__ void qsoft_comb()
{
    int idx = blockIdx.x * blockDim.x + threadIdx.x;
    if (idx >= B_ * C_) return;
    int b = idx >> 8, c = idx & 255;
    float M = -1e30f;
    for (int ch = 0; ch < 16; ch++) M = fmaxf(M, g_pm[(b * 16 + ch) * C_ + c]);
    float S = 0.0f;
    for (int ch = 0; ch < 16; ch++)
        S += g_ps[(b * 16 + ch) * C_ + c] * __expf(g_pm[(b * 16 + ch) * C_ + c] - M);
    g_cmax[idx] = M;
    g_cinv[idx] = 1.0f / S;
}

// ---------------- ctx = softmax_d(k)^T @ v ----------------------------------
__global__ __launch_bounds__(256) void ctx_kernel(const __nv_bfloat16* __restrict__ qkv)
{
    int chunk = blockIdx.x;
    int head  = blockIdx.y;
    int b     = blockIdx.z;
    __shared__ float ks[32][33];
    __shared__ float vs[32][33];
    int tid = threadIdx.x, lane = tid & 31, wp = tid >> 5;
    float acc[4] = {0.f, 0.f, 0.f, 0.f};
    for (int it = 0; it < 8; it++) {
        int nb = chunk * 256 + it * 32;
        #pragma unroll
        for (int j = 0; j < 8; j++) {
            int id = tid + 256 * j;
            int r = id >> 6, inner = id & 63;
            const __nv_bfloat16* src =
                qkv + ((size_t)(b * N_ + nb + r)) * (3 * C_) + C_ + head * D_;
            if (inner < 32) ks[r][inner] = __bfloat162float(src[inner]);
            else            vs[r][inner - 32] = __bfloat162float(src[C_ + inner - 32]);
        }
        __syncthreads();
        #pragma unroll
        for (int rr = 0; rr < 4; rr++) {
            int r = wp * 4 + rr;
            float v = ks[r][lane];
            float mx = v;
            #pragma unroll
            for (int o = 16; o; o >>= 1) mx = fmaxf(mx, __shfl_xor_sync(0xffffffffu, mx, o));
            float e = __expf(v - mx);
            float su = e;
            #pragma unroll
            for (int o = 16; o; o >>= 1) su += __shfl_xor_sync(0xffffffffu, su, o);
            ks[r][lane] = e / su;
        }
        __syncthreads();
        #pragma unroll
        for (int r = 0; r < 32; r++) {
            float vv = vs[r][lane];
            #pragma unroll
            for (int i = 0; i < 4; i++) acc[i] += ks[r][wp + 8 * i] * vv;
        }
        __syncthreads();
    }
    #pragma unroll
    for (int i = 0; i < 4; i++) {
        int e = wp + 8 * i;
        g_ctxp[(size_t)chunk * (B_ * HEADS_ * D_ * D_) +
               ((b * HEADS_ + head) * D_ + e) * D_ + lane] = acc[i];
    }
}

__global__ void ctx_comb()
{
    int idx = blockIdx.x * blockDim.x + threadIdx.x;
    if (idx >= B_ * HEADS_ * D_ * D_) return;
    float s = 0.0f;
    for (int ch = 0; ch < 16; ch++) s += g_ctxp[(size_t)ch * (B_ * HEADS_ * D_ * D_) + idx];
    g_ctx[idx] = s;
}

// ---------------- attn = softmax_N(q) @ ctx ---------------------------------
__global__ __launch_bounds__(256) void attn2(const __nv_bfloat16* __restrict__ qkv,
                                             __nv_bfloat16* __restrict__ out)
{
    int b = blockIdx.y;
    int base = blockIdx.x * 128;
    int h = threadIdx.x >> 5;
    int lane = threadIdx.x & 31;
    int ch = h * 32 + lane;

    float cm = g_cmax[b * C_ + ch];
    float ci = g_cinv[b * C_ + ch];
    float ctxr[32];
    #pragma unroll
    for (int e = 0; e < 32; e++)
        ctxr[e] = g_ctx[((b * HEADS_ + h) * D_ + e) * D_ + lane];

    const __nv_bfloat16* qbase = qkv + (size_t)(b * N_ + base) * (3 * C_) + ch;
    __nv_bfloat16* obase = out + (size_t)(b * N_ + base) * C_ + ch;
    for (int t = 0; t < 128; t++) {
        float q = __bfloat162float(qbase[(size_t)t * (3 * C_)]);
        float p = __expf(q - cm) * ci;
        float acc = 0.0f;
        #pragma unroll
        for (int e = 0; e < 32; e++)
            acc += __shfl_sync(0xffffffffu, p, e) * ctxr[e];
        obase[(size_t)t * C_] = __float2bfloat16_rn(acc);
    }
}

// ---------------- CSDA ------------------------------------------------------
__global__ void cpool_part(const float* __restrict__ x3)
{
    int b = blockIdx.x, ch = blockIdx.y, c = threadIdx.x;
    const float* p = x3 + ((size_t)(b * N_ + ch * 128)) * C_ + c;
    float s = 0.0f, m = -1e30f;
    for (int i = 0; i < 128; i++) {
        float v = p[(size_t)i * C_];
        s += v; m = fmaxf(m, v);
    }
    g_cps[(b * 32 + ch) * C_ + c] = s;
    g_cpm[(b * 32 + ch) * C_ + c] = m;
}

__global__ void cpool_comb()
{
    int idx = blockIdx.x * blockDim.x + threadIdx.x;
    if (idx >= B_ * C_) return;
    int b = idx >> 8, c = idx & 255;
    float s = 0.0f, m = -1e30f;
    for (int ch = 0; ch < 32; ch++) {
        s += g_cps[(b * 32 + ch) * C_ + c];
        m = fmaxf(m, g_cpm[(b * 32 + ch) * C_ + c]);
    }
    g_avg[idx] = s * (1.0f / N_);
    g_mx[idx] = m;
}

__global__ void ca_mlp(const float* __restrict__ w1, const float* __restrict__ w2)
{
    int b = blockIdx.x, t = threadIdx.x;
    __shared__ float hsum[16];
    if (t < 16) {
        float sa = 0.0f, sm = 0.0f;
        for (int c = 0; c < C_; c++) {
            float w = w1[t * C_ + c];
            sa += g_avg[b * C_ + c] * w;
            sm += g_mx[b * C_ + c] * w;
        }
        hsum[t] = fmaxf(sa, 0.0f) + fmaxf(sm, 0.0f);
    }
    __syncthreads();
    float acc = 0.0f;
    #pragma unroll
    for (int j = 0; j < 16; j++) acc += w2[t * 16 + j] * hsum[j];
    g_ca[b * C_ + t] = sigmf(acc);
}

__global__ void spool(const float* __restrict__ x3)
{
    int w = (blockIdx.x * blockDim.x + threadIdx.x) >> 5;
    int lane = threadIdx.x & 31;
    if (w >= ROWS_) return;
    int b = w >> 12;
    const float* r = x3 + (size_t)w * C_;
    const float* ca = g_ca + b * C_;
    float4 a = *(const float4*)(r + lane * 4);
    float4 c0 = *(const float4*)(ca + lane * 4);
    float4 bvals = *(const float4*)(r + 128 + lane * 4);
    float4 c1 = *(const float4*)(ca + 128 + lane * 4);
    float v0 = a.x * c0.x, v1 = a.y * c0.y, v2 = a.z * c0.z, v3 = a.w * c0.w;
    float v4 = bvals.x * c1.x, v5 = bvals.y * c1.y, v6 = bvals.z * c1.z, v7 = bvals.w * c1.w;
    float s = v0 + v1 + v2 + v3 + v4 + v5 + v6 + v7;
    float m = fmaxf(fmaxf(fmaxf(v0, v1), fmaxf(v2, v3)), fmaxf(fmaxf(v4, v5), fmaxf(v6, v7)));
    #pragma unroll
    for (int o = 16; o; o >>= 1) {
        s += __shfl_xor_sync(0xffffffffu, s, o);
        m = fmaxf(m, __shfl_xor_sync(0xffffffffu, m, o));
    }
    if (lane == 0) {
        g_sm[w] = s * (1.0f / C_);
        g_sx[w] = m;
    }
}

__global__ void conv7(const float* __restrict__ spw, const float* __restrict__ spb)
{
    int idx = blockIdx.x * blockDim.x + threadIdx.x;
    if (idx >= ROWS_) return;
    int b = idx >> 12, n = idx & 4095;
    int h = n >> 6, w = n & 63;
    float acc = spb[0];
    #pragma unroll
    for (int ch = 0; ch < 2; ch++) {
        const float* src = ch ? g_sx : g_sm;
        const float* wp = spw + ch * 49;
        for (int ky = 0; ky < 7; ky++) {
            int y = h + ky - 3;
            if ((unsigned)y >= 64u) continue;
            for (int kx = 0; kx < 7; kx++) {
                int x = w + kx - 3;
                if ((unsigned)x >= 64u) continue;
                acc += src[(b << 12) + (y << 6) + x] * wp[ky * 7 + kx];
            }
        }
    }
    g_sa[idx] = sigmf(acc);
}

__global__ void final_scale(const float* __restrict__ x3, float* __restrict__ out)
{
    int idx = blockIdx.x * blockDim.x + threadIdx.x;
    if (idx >= ROWS_ * 64) return;
    int c4 = idx & 63;
    int row = idx >> 6;
    int b = row >> 12;
    float4 v = *(const float4*)(x3 + (size_t)row * C_ + c4 * 4);
    float4 ca = *(const float4*)(g_ca + b * C_ + c4 * 4);
    float sa = g_sa[row];
    v.x *= ca.x * sa; v.y *= ca.y * sa; v.z *= ca.z * sa; v.w *= ca.w * sa;
    *(float4*)(out + (size_t)row * C_ + c4 * 4) = v;
}

// ---------------------------------------------------------------------------
extern "C" void kernel_launch(void* const* d_in, const int* in_sizes, int n_in,
                              void* d_out, int out_size)
{
    int p = (n_in >= 24 && in_sizes[1] == 1 && in_sizes[2] == 1) ? 3 : 1;
    const float* x      = (const float*)d_in[0];
    const float* n1_g   = (const float*)d_in[p + 0];
    const float* n1_b   = (const float*)d_in[p + 1];
    const float* sr_w   = (const float*)d_in[p + 2];
    const float* sr_b   = (const float*)d_in[p + 3];
    const float* an_g   = (const float*)d_in[p + 4];
    const float* an_b   = (const float*)d_in[p + 5];
    const float* qkv_w  = (const float*)d_in[p + 6];
    const float* proj_w = (const float*)d_in[p + 7];
    const float* proj_b = (const float*)d_in[p + 8];
    const float* n2_g   = (const float*)d_in[p + 9];
    const float* n2_b   = (const float*)d_in[p + 10];
    const float* fc1_w  = (const float*)d_in[p + 11];
    const float* fc1_b  = (const float*)d_in[p + 12];
    const float* dw_w   = (const float*)d_in[p + 13];
    const float* dw_b   = (const float*)d_in[p + 14];
    const float* fc2_w  = (const float*)d_in[p + 15];
    const float* fc2_b  = (const float*)d_in[p + 16];
    const float* ca_w1  = (const float*)d_in[p + 17];
    const float* ca_w2  = (const float*)d_in[p + 18];
    const float* sp_w   = (const float*)d_in[p + 19];
    const float* sp_b   = (const float*)d_in[p + 20];
    float* out = (float*)d_out;

    float *pxn, *pb1, *pb2;
    __nv_bfloat16 *pqkv16, *pa16, *ph16a, *ph16b, *pw16;
    cudaGetSymbolAddress((void**)&pxn,    g_xn);
    cudaGetSymbolAddress((void**)&pb1,    g_b1);
    cudaGetSymbolAddress((void**)&pb2,    g_b2);
    cudaGetSymbolAddress((void**)&pqkv16, g_qkv16);
    cudaGetSymbolAddress((void**)&pa16,   g_a16);
    cudaGetSymbolAddress((void**)&ph16a,  g_h16a);
    cudaGetSymbolAddress((void**)&ph16b,  g_h16b);
    cudaGetSymbolAddress((void**)&pw16,   g_w16);

    const int TPB = 256;
    const int GEMM_SMEM = 4 * HTILE * 2;   // 73728 bytes
    cudaFuncSetAttribute(gemm_bf16<float>, cudaFuncAttributeMaxDynamicSharedMemorySize,
                         GEMM_SMEM);
    cudaFuncSetAttribute(gemm_bf16<__nv_bfloat16>, cudaFuncAttributeMaxDynamicSharedMemorySize,
                         GEMM_SMEM);

    // 0. bf16 weight conversion (one kernel)
    f2bf_all<<<(393216 + TPB - 1) / TPB, TPB>>>(qkv_w, proj_w, fc1_w, fc2_w, pw16);

    // 1. xn = LN1(x)
    ln256<float><<<ROWS_ * 32 / TPB, TPB>>>(x, pxn, n1_g, n1_b);
    // 2+3. xa16 = bf16(xn + gelu(LN_act(dwconv3(xn))))  (fused)
    sr_fuse<<<ROWS_, TPB>>>(pxn, pa16, sr_w, sr_b, an_g, an_b);
    // 4. qkv = xa @ qkv_w^T  (bf16 out)
    {
        dim3 g(3 * C_ / 128, ROWS_ / 128);
        gemm_bf16<__nv_bfloat16><<<g, TPB, GEMM_SMEM>>>(pa16, pw16 + W16_QKV, pqkv16,
                                                        ROWS_, 3 * C_, C_, nullptr, nullptr, nullptr);
    }
    // 5. q column-softmax stats
    {
        dim3 g(B_, 16);
        qsoft_part<<<g, TPB>>>(pqkv16);
        qsoft_comb<<<(B_ * C_ + TPB - 1) / TPB, TPB>>>();
    }
    // 6. ctx = softmax_d(k)^T v
    {
        dim3 g(16, HEADS_, B_);
        ctx_kernel<<<g, TPB>>>(pqkv16);
        ctx_comb<<<(B_ * HEADS_ * D_ * D_ + TPB - 1) / TPB, TPB>>>();
    }
    // 7. attn = softmax_N(q) @ ctx -> a16 (bf16)
    {
        dim3 g(N_ / 128, B_);
        attn2<<<g, TPB>>>(pqkv16, pa16);
    }
    // 8. x2 = x + attn @ proj_w^T + proj_b + xn -> b1
    {
        dim3 g(C_ / 128, ROWS_ / 128);
        gemm_bf16<float><<<g, TPB, GEMM_SMEM>>>(pa16, pw16 + W16_PROJ, pb1,
                                                ROWS_, C_, C_, proj_b, x, pxn);
    }
    // 9. ln2(x2) -> a16 (bf16)
    ln256<__nv_bfloat16><<<ROWS_ * 32 / TPB, TPB>>>(pb1, pa16, n2_g, n2_b);
    // 10. fc1 -> h16a (bf16)
    {
        dim3 g(HID_ / 128, ROWS_ / 128);
        gemm_bf16<__nv_bfloat16><<<g, TPB, GEMM_SMEM>>>(pa16, pw16 + W16_FC1, ph16a,
                                                        ROWS_, HID_, C_, fc1_b, nullptr, nullptr);
    }
    // 11. dwconv + gelu (bf16, sliding window) -> h16b
    {
        dim3 g(HID_ / 4 / 16, 64, B_);
        dwconv3_bf16_v2<<<g, TPB>>>(ph16a, ph16b, dw_w, dw_b);
    }
    // 12. x3 = x2 + gelu_dw @ fc2_w^T + fc2_b -> b2
    {
        dim3 g(C_ / 128, ROWS_ / 128);
        gemm_bf16<float><<<g, TPB, GEMM_SMEM>>>(ph16b, pw16 + W16_FC2, pb2,
                                                ROWS_, C_, HID_, fc2_b, pb1, nullptr);
    }
    // 13. channel pools
    {
        dim3 g(B_, 32);
        cpool_part<<<g, TPB>>>(pb2);
        cpool_comb<<<(B_ * C_ + TPB - 1) / TPB, TPB>>>();
    }
    // 14. channel attention MLP
    ca_mlp<<<B_, TPB>>>(ca_w1, ca_w2);
    // 15. spatial pools of x3*ca
    spool<<<ROWS_ * 32 / TPB, TPB>>>(pb2);
    // 16. 7x7 spatial conv -> sa
    conv7<<<(ROWS_ + TPB - 1) / TPB, TPB>>>(sp_w, sp_b);
    // 17. out = x3 * ca * sa
    final_scale<<<(ROWS_ * 64 + TPB - 1) / TPB, TPB>>>(pb2, out);
}

// round 7
// speedup vs baseline: 4.4384x; 1.0423x over previous
#include <cuda_runtime.h>
#include <cuda_bf16.h>
#include <math.h>
#include <stdint.h>

// Problem constants
#define B_    16
#define N_    4096
#define C_    256
#define HEADS_ 8
#define D_    32
#define HID_  1024
#define ROWS_ 65536          // B_*N_

// ---------------- scratch (device globals; no allocation allowed) ----------
__device__ float g_xn  [ROWS_ * C_];           // norm1(x)
__device__ float g_b1  [ROWS_ * C_];           // x2
__device__ float g_b2  [ROWS_ * C_];           // x3
__device__ __nv_bfloat16 g_qkv16[ROWS_ * 3 * C_]; // qkv (bf16)
__device__ __nv_bfloat16 g_a16 [ROWS_ * C_];   // xa / attn / ln2 (bf16, reused)
__device__ __nv_bfloat16 g_h16a[ROWS_ * HID_]; // fc1 out (bf16)
__device__ __nv_bfloat16 g_h16b[ROWS_ * HID_]; // dwconv+gelu out (bf16)
__device__ __nv_bfloat16 g_w16 [786432];       // bf16 weights (qkv|proj|fc1|fc2)
#define W16_QKV  0
#define W16_PROJ 196608
#define W16_FC1  262144
#define W16_FC2  524288
__device__ float g_pm  [B_ * 64 * C_];
__device__ float g_ps  [B_ * 64 * C_];
__device__ float g_cmax[B_ * C_];
__device__ float g_cinv[B_ * C_];
__device__ float g_ctxp[16 * B_ * HEADS_ * D_ * D_];
__device__ float g_ctx [B_ * HEADS_ * D_ * D_];
__device__ float g_cps [B_ * 64 * C_];
__device__ float g_cpm [B_ * 64 * C_];
__device__ float g_avg [B_ * C_];
__device__ float g_mx  [B_ * C_];
__device__ float g_ca  [B_ * C_];
__device__ float g_sm  [ROWS_];
__device__ float g_sx  [ROWS_];
__device__ float g_sa  [ROWS_];

__device__ __forceinline__ float geluf(float x) {
    return 0.5f * x * (1.0f + erff(x * 0.70710678118654752440f));
}
__device__ __forceinline__ float sigmf(float x) {
    return 1.0f / (1.0f + __expf(-x));
}
__device__ __forceinline__ void store8(float* p, float4 v) { *(float4*)p = v; }
__device__ __forceinline__ void store8(__nv_bfloat16* p, float4 v) {
    __nv_bfloat162 h0 = __floats2bfloat162_rn(v.x, v.y);
    __nv_bfloat162 h1 = __floats2bfloat162_rn(v.z, v.w);
    uint2 u;
    u.x = *reinterpret_cast<uint32_t*>(&h0);
    u.y = *reinterpret_cast<uint32_t*>(&h1);
    *(uint2*)p = u;
}

// ---------------- fp32 -> bf16 weight conversion (all 4 weights, 1 kernel) --
__global__ void f2bf_all(const float* __restrict__ s0, const float* __restrict__ s1,
                         const float* __restrict__ s2, const float* __restrict__ s3,
                         __nv_bfloat16* __restrict__ dst)
{
    int i = blockIdx.x * blockDim.x + threadIdx.x;
    if (i >= 393216) return;
    int e = i * 2;
    const float* src;
    int off;
    if (e < W16_PROJ)      { src = s0; off = e; }
    else if (e < W16_FC1)  { src = s1; off = e - W16_PROJ; }
    else if (e < W16_FC2)  { src = s2; off = e - W16_FC1; }
    else                   { src = s3; off = e - W16_FC2; }
    float2 v = *(const float2*)(src + off);
    __nv_bfloat162 h = __floats2bfloat162_rn(v.x, v.y);
    *(uint32_t*)(dst + e) = *reinterpret_cast<uint32_t*>(&h);
}

// ---------------- LayerNorm (256 wide), one warp per row --------------------
template <typename OutT>
__global__ void ln256(const float* __restrict__ in, OutT* __restrict__ out,
                      const float* __restrict__ g, const float* __restrict__ bt)
{
    int w = (blockIdx.x * blockDim.x + threadIdx.x) >> 5;
    int lane = threadIdx.x & 31;
    if (w >= ROWS_) return;
    const float* r = in + (size_t)w * C_;
    float4 a = *(const float4*)(r + lane * 4);
    float4 b = *(const float4*)(r + 128 + lane * 4);
    float s = a.x + a.y + a.z + a.w + b.x + b.y + b.z + b.w;
    float q = a.x*a.x + a.y*a.y + a.z*a.z + a.w*a.w
            + b.x*b.x + b.y*b.y + b.z*b.z + b.w*b.w;
    #pragma unroll
    for (int o = 16; o; o >>= 1) {
        s += __shfl_xor_sync(0xffffffffu, s, o);
        q += __shfl_xor_sync(0xffffffffu, q, o);
    }
    float mean = s * (1.0f / C_);
    float inv = rsqrtf(q * (1.0f / C_) - mean * mean + 1e-5f);
    float4 g0 = *(const float4*)(g + lane * 4);
    float4 g1 = *(const float4*)(g + 128 + lane * 4);
    float4 b0 = *(const float4*)(bt + lane * 4);
    float4 b1 = *(const float4*)(bt + 128 + lane * 4);
    float4 o0, o1;
    o0.x = (a.x - mean) * inv * g0.x + b0.x;
    o0.y = (a.y - mean) * inv * g0.y + b0.y;
    o0.z = (a.z - mean) * inv * g0.z + b0.z;
    o0.w = (a.w - mean) * inv * g0.w + b0.w;
    o1.x = (b.x - mean) * inv * g1.x + b1.x;
    o1.y = (b.y - mean) * inv * g1.y + b1.y;
    o1.z = (b.z - mean) * inv * g1.z + b1.z;
    o1.w = (b.w - mean) * inv * g1.w + b1.w;
    OutT* po = out + (size_t)w * C_;
    store8(po + lane * 4, o0);
    store8(po + 128 + lane * 4, o1);
}

// --------- fused: dwconv3(xn) -> LN -> gelu -> +xn -> bf16 out --------------
__global__ __launch_bounds__(256)
void sr_fuse(const float* __restrict__ xn, __nv_bfloat16* __restrict__ out,
             const float* __restrict__ sw, const float* __restrict__ sb,
             const float* __restrict__ ag, const float* __restrict__ ab)
{
    __shared__ float red[16];
    int n = blockIdx.x;
    int b = n >> 12, pos = n & 4095;
    int h = pos >> 6, w = pos & 63;
    int c = threadIdx.x;
    float acc = sb[c];
    #pragma unroll
    for (int dy = -1; dy <= 1; dy++) {
        int hh = h + dy;
        if ((unsigned)hh >= 64u) continue;
        #pragma unroll
        for (int dx = -1; dx <= 1; dx++) {
            int ww = w + dx;
            if ((unsigned)ww >= 64u) continue;
            int k = (dy + 1) * 3 + (dx + 1);
            acc += xn[((size_t)(b * N_ + (hh << 6) + ww)) * C_ + c] * sw[c * 9 + k];
        }
    }
    float s = acc, q = acc * acc;
    #pragma unroll
    for (int o = 16; o; o >>= 1) {
        s += __shfl_xor_sync(0xffffffffu, s, o);
        q += __shfl_xor_sync(0xffffffffu, q, o);
    }
    int wid = c >> 5, lane = c & 31;
    if (lane == 0) { red[wid] = s; red[8 + wid] = q; }
    __syncthreads();
    if (wid == 0) {
        float ss = (lane < 8) ? red[lane] : 0.0f;
        float qq = (lane < 8) ? red[8 + lane] : 0.0f;
        #pragma unroll
        for (int o = 4; o; o >>= 1) {
            ss += __shfl_xor_sync(0xffffffffu, ss, o);
            qq += __shfl_xor_sync(0xffffffffu, qq, o);
        }
        if (lane == 0) { red[0] = ss; red[1] = qq; }
    }
    __syncthreads();
    float mean = red[0] * (1.0f / C_);
    float inv = rsqrtf(red[1] * (1.0f / C_) - mean * mean + 1e-5f);
    float v = (acc - mean) * inv * ag[c] + ab[c];
    float xa = xn[(size_t)n * C_ + c] + geluf(v);
    out[(size_t)n * C_ + c] = __float2bfloat16_rn(xa);
}

// --------- depthwise 3x3 bf16 + gelu, 4-token sliding window ----------------
__global__ __launch_bounds__(256)
void dwconv3_bf16_v2(const __nv_bfloat16* __restrict__ in,
                     __nv_bfloat16* __restrict__ out,
                     const float* __restrict__ w, const float* __restrict__ bias)
{
    const int CH = HID_;
    int tid = threadIdx.x;
    int c0 = (blockIdx.x * 16 + (tid & 15)) * 4;
    int h  = blockIdx.y;
    int b  = blockIdx.z;
    int w0 = (tid >> 4) * 4;

    float wr[4][9];
    #pragma unroll
    for (int i = 0; i < 4; i++)
        #pragma unroll
        for (int k = 0; k < 9; k++)
            wr[i][k] = w[(c0 + i) * 9 + k];

    float acc[4][4];
    #pragma unroll
    for (int t = 0; t < 4; t++)
        #pragma unroll
        for (int i = 0; i < 4; i++)
            acc[t][i] = bias[c0 + i];

    #pragma unroll
    for (int dy = -1; dy <= 1; dy++) {
        int hh = h + dy;
        if ((unsigned)hh >= 64u) continue;
        const __nv_bfloat16* rowp = in + ((size_t)(b * N_ + (hh << 6))) * CH + c0;
        #pragma unroll
        for (int wx = -1; wx <= 4; wx++) {
            int ww = w0 + wx;
            if ((unsigned)ww >= 64u) continue;
            uint2 raw = *(const uint2*)(rowp + (size_t)ww * CH);
            float2 f0 = __bfloat1622float2(*reinterpret_cast<__nv_bfloat162*>(&raw.x));
            float2 f1 = __bfloat1622float2(*reinterpret_cast<__nv_bfloat162*>(&raw.y));
            float f[4] = {f0.x, f0.y, f1.x, f1.y};
            #pragma unroll
            for (int t = 0; t < 4; t++) {
                int kx = wx - t;
                if (kx < -1 || kx > 1) continue;
                int k = (dy + 1) * 3 + kx + 1;
                #pragma unroll
                for (int i = 0; i < 4; i++)
                    acc[t][i] += f[i] * wr[i][k];
            }
        }
    }
    #pragma unroll
    for (int t = 0; t < 4; t++) {
        float4 o = make_float4(geluf(acc[t][0]), geluf(acc[t][1]),
                               geluf(acc[t][2]), geluf(acc[t][3]));
        store8(out + ((size_t)(b * N_ + (h << 6) + w0 + t)) * CH + c0, o);
    }
}

// -------- BF16 GEMM, 3-stage cp.async pipeline, XOR-swizzled smem -----------
// tile 128x128x64; 8 warps (2m x 4n); warp 64x32 via m16n8k16 + ldmatrix.
// smem row = 64 halves = 128B = 8 chunks of 16B; chunk ^= (row & 7).
#define SSTG 16384                 // bytes per stage per matrix
#define NSTAGE 3

__device__ __forceinline__ void cp16(uint32_t d, const void* s) {
    asm volatile("cp.async.cg.shared.global [%0], [%1], 16;" :: "r"(d), "l"(s));
}

template <typename OutT>
__global__ __launch_bounds__(256, 2)
void gemm_bf16(const __nv_bfloat16* __restrict__ A, const __nv_bfloat16* __restrict__ W,
               OutT* __restrict__ Cout, int M, int N, int K,
               const float* __restrict__ bias,
               const float* __restrict__ r1, const float* __restrict__ r2)
{
    extern __shared__ __nv_bfloat16 sh16[];
    uint32_t sA0 = (uint32_t)__cvta_generic_to_shared(sh16);
    uint32_t sB0 = sA0 + NSTAGE * SSTG;

    int tid = threadIdx.x;
    int warp = tid >> 5, lane = tid & 31;
    int wm = warp >> 2, wn = warp & 3;
    int bm = blockIdx.y * 128, bn = blockIdx.x * 128;
    int gr = lane >> 2, gc = lane & 3;

    float acc[4][4][4];
    #pragma unroll
    for (int i = 0; i < 4; i++)
        #pragma unroll
        for (int j = 0; j < 4; j++)
            #pragma unroll
            for (int q = 0; q < 4; q++) acc[i][j][q] = 0.0f;

    int KT = K >> 6;

    // loader: thread -> (row ldr, 16B chunk)
    int ldr = tid >> 3;
    int chk = tid & 7;
    uint32_t swd = (uint32_t)(ldr * 128 + ((chk ^ (ldr & 7)) << 4));
    const __nv_bfloat16* Abase = A + (size_t)(bm + ldr) * K + chk * 8;
    const __nv_bfloat16* Wbase = W + (size_t)(bn + ldr) * K + chk * 8;

    #define LOAD_STAGE(st, kb) do {                                            \
        uint32_t so = (st) * SSTG + swd;                                       \
        size_t go = (size_t)(kb) * 64;                                         \
        _Pragma("unroll")                                                      \
        for (int it = 0; it < 4; it++) {                                       \
            cp16(sA0 + so + it * 4096, Abase + (size_t)(it * 32) * K + go);    \
            cp16(sB0 + so + it * 4096, Wbase + (size_t)(it * 32) * K + go);    \
        }                                                                      \
        asm volatile("cp.async.commit_group;");                                \
    } while (0)

    LOAD_STAGE(0, 0);
    if (KT > 1) LOAD_STAGE(1, 1);

    // ldmatrix lane bases
    int rA = wm * 64 + (lane & 15);          // row&7 invariant across i*16
    int cAx = lane >> 4;                     // 0/1 chunk within k-step
    int sa7 = rA & 7;
    int rB = wn * 32 + (lane & 7);
    int cBx = (lane >> 3) & 1;
    int sb7 = rB & 7;

    int st = 0;
    for (int kb = 0; kb < KT; kb++) {
        asm volatile("cp.async.wait_group 1;");
        __syncthreads();

        uint32_t stA = sA0 + st * SSTG;
        uint32_t stB = sB0 + st * SSTG;
        #pragma unroll
        for (int ks = 0; ks < 4; ks++) {
            uint32_t a[4][4], b[4][2];
            uint32_t ca = (uint32_t)(((ks * 2 + cAx) ^ sa7) << 4);
            uint32_t cb = (uint32_t)(((ks * 2 + cBx) ^ sb7) << 4);
            #pragma unroll
            for (int i = 0; i < 4; i++) {
                uint32_t addr = stA + (uint32_t)((rA + i * 16) * 128) + ca;
                asm volatile(
                    "ldmatrix.sync.aligned.m8n8.x4.shared.b16 {%0,%1,%2,%3}, [%4];"
                    : "=r"(a[i][0]), "=r"(a[i][1]), "=r"(a[i][2]), "=r"(a[i][3])
                    : "r"(addr));
            }
            #pragma unroll
            for (int j = 0; j < 4; j++) {
                uint32_t addr = stB + (uint32_t)((rB + j * 8) * 128) + cb;
                asm volatile(
                    "ldmatrix.sync.aligned.m8n8.x2.shared.b16 {%0,%1}, [%2];"
                    : "=r"(b[j][0]), "=r"(b[j][1])
                    : "r"(addr));
            }
            #pragma unroll
            for (int i = 0; i < 4; i++)
                #pragma unroll
                for (int j = 0; j < 4; j++)
                    asm volatile(
                        "mma.sync.aligned.m16n8k16.row.col.f32.bf16.bf16.f32 "
                        "{%0,%1,%2,%3}, {%4,%5,%6,%7}, {%8,%9}, {%0,%1,%2,%3};"
                        : "+f"(acc[i][j][0]), "+f"(acc[i][j][1]),
                          "+f"(acc[i][j][2]), "+f"(acc[i][j][3])
                        : "r"(a[i][0]), "r"(a[i][1]), "r"(a[i][2]), "r"(a[i][3]),
                          "r"(b[j][0]), "r"(b[j][1]));
        }
        if (kb + 2 < KT) {
            int nst = st + 2; if (nst >= NSTAGE) nst -= NSTAGE;
            LOAD_STAGE(nst, kb + 2);
        }
        st++; if (st == NSTAGE) st = 0;
    }

    #pragma unroll
    for (int i = 0; i < 4; i++) {
        int row0 = bm + wm * 64 + i * 16 + gr;
        #pragma unroll
        for (int j = 0; j < 4; j++) {
            int col = bn + wn * 32 + j * 8 + gc * 2;
            float bx = 0.f, by = 0.f;
            if (bias) { bx = bias[col]; by = bias[col + 1]; }
            size_t o0 = (size_t)row0 * N + col;
            size_t o1 = (size_t)(row0 + 8) * N + col;
            float v0 = acc[i][j][0] + bx, v1 = acc[i][j][1] + by;
            float v2 = acc[i][j][2] + bx, v3 = acc[i][j][3] + by;
            if (r1) {
                float2 p0 = *(const float2*)(r1 + o0);
                float2 p1 = *(const float2*)(r1 + o1);
                v0 += p0.x; v1 += p0.y; v2 += p1.x; v3 += p1.y;
            }
            if (r2) {
                float2 p0 = *(const float2*)(r2 + o0);
                float2 p1 = *(const float2*)(r2 + o1);
                v0 += p0.x; v1 += p0.y; v2 += p1.x; v3 += p1.y;
            }
            if constexpr (sizeof(OutT) == 4) {
                *(float2*)((float*)Cout + o0) = make_float2(v0, v1);
                *(float2*)((float*)Cout + o1) = make_float2(v2, v3);
            } else {
                __nv_bfloat162 h0 = __floats2bfloat162_rn(v0, v1);
                __nv_bfloat162 h1 = __floats2bfloat162_rn(v2, v3);
                *(uint32_t*)((__nv_bfloat16*)Cout + o0) = *reinterpret_cast<uint32_t*>(&h0);
                *(uint32_t*)((__nv_bfloat16*)Cout + o1) = *reinterpret_cast<uint32_t*>(&h1);
            }
        }
    }
}

// ---------------- q softmax over tokens: per-(b,c) online partials ----------
__global__ void qsoft_part(const __nv_bfloat16* __restrict__ qkv)
{
    int b = blockIdx.x, ch = blockIdx.y, c = threadIdx.x;   // 64 chunks of 64
    const __nv_bfloat16* p = qkv + ((size_t)(b * N_ + ch * 64)) * (3 * C_) + c;
    float m = -1e30f, s = 0.0f;
    for (int i = 0; i < 64; i++) {
        float v = __bfloat162float(p[(size_t)i * (3 * C_)]);
        float nm = fmaxf(m, v);
        s = s * __expf(m - nm) + __expf(v - nm);
        m = nm;
    }
    g_pm[(b * 64 + ch) * C_ + c] = m;
    g_ps[(b * 64 + ch) * C_ + c] = s;
}

__global__ void qsoft_comb()
{
    int idx = blockIdx.x * blockDim.x + threadIdx.x;
    if (idx >= B_ * C_) return;
    int b = idx >> 8, c = idx & 255;
    float M = -1e30f;
    for (int ch = 0; ch < 64; ch++) M = fmaxf(M, g_pm[(b * 64 + ch) * C_ + c]);
    float S = 0.0f;
    for (int ch = 0; ch < 64; ch++)
        S += g_ps[(b * 64 + ch) * C_ + c] * __expf(g_pm[(b * 64 + ch) * C_ + c] - M);
    g_cmax[idx] = M;
    g_cinv[idx] = 1.0f / S;
}

// ---------------- ctx = softmax_d(k)^T @ v ----------------------------------
__global__ __launch_bounds__(256) void ctx_kernel(const __nv_bfloat16* __restrict__ qkv)
{
    int chunk = blockIdx.x;
    int head  = blockIdx.y;
    int b     = blockIdx.z;
    __shared__ float ks[32][33];
    __shared__ float vs[32][33];
    int tid = threadIdx.x, lane = tid & 31, wp = tid >> 5;
    float acc[4] = {0.f, 0.f, 0.f, 0.f};
    for (int it = 0; it < 8; it++) {
        int nb = chunk * 256 + it * 32;
        #pragma unroll
        for (int j = 0; j < 8; j++) {
            int id = tid + 256 * j;
            int r = id >> 6, inner = id & 63;
            const __nv_bfloat16* src =
                qkv + ((size_t)(b * N_ + nb + r)) * (3 * C_) + C_ + head * D_;
            if (inner < 32) ks[r][inner] = __bfloat162float(src[inner]);
            else            vs[r][inner - 32] = __bfloat162float(src[C_ + inner - 32]);
        }
        __syncthreads();
        #pragma unroll
        for (int rr = 0; rr < 4; rr++) {
            int r = wp * 4 + rr;
            float v = ks[r][lane];
            float mx = v;
            #pragma unroll
            for (int o = 16; o; o >>= 1) mx = fmaxf(mx, __shfl_xor_sync(0xffffffffu, mx, o));
            float e = __expf(v - mx);
            float su = e;
            #pragma unroll
            for (int o = 16; o; o >>= 1) su += __shfl_xor_sync(0xffffffffu, su, o);
            ks[r][lane] = e / su;
        }
        __syncthreads();
        #pragma unroll
        for (int r = 0; r < 32; r++) {
            float vv = vs[r][lane];
            #pragma unroll
            for (int i = 0; i < 4; i++) acc[i] += ks[r][wp + 8 * i] * vv;
        }
        __syncthreads();
    }
    #pragma unroll
    for (int i = 0; i < 4; i++) {
        int e = wp + 8 * i;
        g_ctxp[(size_t)chunk * (B_ * HEADS_ * D_ * D_) +
               ((b * HEADS_ + head) * D_ + e) * D_ + lane] = acc[i];
    }
}

__global__ void ctx_comb()
{
    int idx = blockIdx.x * blockDim.x + threadIdx.x;
    if (idx >= B_ * HEADS_ * D_ * D_) return;
    float s = 0.0f;
    for (int ch = 0; ch < 16; ch++) s += g_ctxp[(size_t)ch * (B_ * HEADS_ * D_ * D_) + idx];
    g_ctx[idx] = s;
}

// ---------------- attn = softmax_N(q) @ ctx ---------------------------------
__global__ __launch_bounds__(256) void attn2(const __nv_bfloat16* __restrict__ qkv,
                                             __nv_bfloat16* __restrict__ out)
{
    int b = blockIdx.y;
    int base = blockIdx.x * 64;             // 64 tokens per block
    int h = threadIdx.x >> 5;
    int lane = threadIdx.x & 31;
    int ch = h * 32 + lane;

    float cm = g_cmax[b * C_ + ch];
    float ci = g_cinv[b * C_ + ch];
    float ctxr[32];
    #pragma unroll
    for (int e = 0; e < 32; e++)
        ctxr[e] = g_ctx[((b * HEADS_ + h) * D_ + e) * D_ + lane];

    const __nv_bfloat16* qbase = qkv + (size_t)(b * N_ + base) * (3 * C_) + ch;
    __nv_bfloat16* obase = out + (size_t)(b * N_ + base) * C_ + ch;
    for (int t = 0; t < 64; t++) {
        float q = __bfloat162float(qbase[(size_t)t * (3 * C_)]);
        float p = __expf(q - cm) * ci;
        float acc = 0.0f;
        #pragma unroll
        for (int e = 0; e < 32; e++)
            acc += __shfl_sync(0xffffffffu, p, e) * ctxr[e];
        obase[(size_t)t * C_] = __float2bfloat16_rn(acc);
    }
}

// ---------------- CSDA ------------------------------------------------------
__global__ void cpool_part(const float* __restrict__ x3)
{
    int b = blockIdx.x, ch = blockIdx.y, c = threadIdx.x;   // 64 chunks of 64
    const float* p = x3 + ((size_t)(b * N_ + ch * 64)) * C_ + c;
    float s = 0.0f, m = -1e30f;
    for (int i = 0; i < 64; i++) {
        float v = p[(size_t)i * C_];
        s += v; m = fmaxf(m, v);
    }
    g_cps[(b * 64 + ch) * C_ + c] = s;
    g_cpm[(b * 64 + ch) * C_ + c] = m;
}

__global__ void cpool_comb()
{
    int idx = blockIdx.x * blockDim.x + threadIdx.x;
    if (idx >= B_ * C_) return;
    int b = idx >> 8, c = idx & 255;
    float s = 0.0f, m = -1e30f;
    for (int ch = 0; ch < 64; ch++) {
        s += g_cps[(b * 64 + ch) * C_ + c];
        m = fmaxf(m, g_cpm[(b * 64 + ch) * C_ + c]);
    }
    g_avg[idx] = s * (1.0f / N_);
    g_mx[idx] = m;
}

__global__ void ca_mlp(const float* __restrict__ w1, const float* __restrict__ w2)
{
    int b = blockIdx.x, t = threadIdx.x;
    __shared__ float hsum[16];
    if (t < 16) {
        float sa = 0.0f, sm = 0.0f;
        for (int c = 0; c < C_; c++) {
            float w = w1[t * C_ + c];
            sa += g_avg[b * C_ + c] * w;
            sm += g_mx[b * C_ + c] * w;
        }
        hsum[t] = fmaxf(sa, 0.0f) + fmaxf(sm, 0.0f);
    }
    __syncthreads();
    float acc = 0.0f;
    #pragma unroll
    for (int j = 0; j < 16; j++) acc += w2[t * 16 + j] * hsum[j];
    g_ca[b * C_ + t] = sigmf(acc);
}

__global__ void spool(const float* __restrict__ x3)
{
    int w = (blockIdx.x * blockDim.x + threadIdx.x) >> 5;
    int lane = threadIdx.x & 31;
    if (w >= ROWS_) return;
    int b = w >> 12;
    const float* r = x3 + (size_t)w * C_;
    const float* ca = g_ca + b * C_;
    float4 a = *(const float4*)(r + lane * 4);
    float4 c0 = *(const float4*)(ca + lane * 4);
    float4 bvals = *(const float4*)(r + 128 + lane * 4);
    float4 c1 = *(const float4*)(ca + 128 + lane * 4);
    float v0 = a.x * c0.x, v1 = a.y * c0.y, v2 = a.z * c0.z, v3 = a.w * c0.w;
    float v4 = bvals.x * c1.x, v5 = bvals.y * c1.y, v6 = bvals.z * c1.z, v7 = bvals.w * c1.w;
    float s = v0 + v1 + v2 + v3 + v4 + v5 + v6 + v7;
    float m = fmaxf(fmaxf(fmaxf(v0, v1), fmaxf(v2, v3)), fmaxf(fmaxf(v4, v5), fmaxf(v6, v7)));
    #pragma unroll
    for (int o = 16; o; o >>= 1) {
        s += __shfl_xor_sync(0xffffffffu, s, o);
        m = fmaxf(m, __shfl_xor_sync(0xffffffffu, m, o));
    }
    if (lane == 0) {
        g_sm[w] = s * (1.0f / C_);
        g_sx[w] = m;
    }
}

__global__ void conv7(const float* __restrict__ spw, const float* __restrict__ spb)
{
    int idx = blockIdx.x * blockDim.x + threadIdx.x;
    if (idx >= ROWS_) return;
    int b = idx >> 12, n = idx & 4095;
    int h = n >> 6, w = n & 63;
    float acc = spb[0];
    #pragma unroll
    for (int ch = 0; ch < 2; ch++) {
        const float* src = ch ? g_sx : g_sm;
        const float* wp = spw + ch * 49;
        for (int ky = 0; ky < 7; ky++) {
            int y = h + ky - 3;
            if ((unsigned)y >= 64u) continue;
            for (int kx = 0; kx < 7; kx++) {
                int x = w + kx - 3;
                if ((unsigned)x >= 64u) continue;
                acc += src[(b << 12) + (y << 6) + x] * wp[ky * 7 + kx];
            }
        }
    }
    g_sa[idx] = sigmf(acc);
}

__global__ void final_scale(const float* __restrict__ x3, float* __restrict__ out)
{
    int idx = blockIdx.x * blockDim.x + threadIdx.x;
    if (idx >= ROWS_ * 64) return;
    int c4 = idx & 63;
    int row = idx >> 6;
    int b = row >> 12;
    float4 v = *(const float4*)(x3 + (size_t)row * C_ + c4 * 4);
    float4 ca = *(const float4*)(g_ca + b * C_ + c4 * 4);
    float sa = g_sa[row];
    v.x *= ca.x * sa; v.y *= ca.y * sa; v.z *= ca.z * sa; v.w *= ca.w * sa;
    *(float4*)(out + (size_t)row * C_ + c4 * 4) = v;
}

// ---------------------------------------------------------------------------
extern "C" void kernel_launch(void* const* d_in, const int* in_sizes, int n_in,
                              void* d_out, int out_size)
{
    int p = (n_in >= 24 && in_sizes[1] == 1 && in_sizes[2] == 1) ? 3 : 1;
    const float* x      = (const float*)d_in[0];
    const float* n1_g   = (const float*)d_in[p + 0];
    const float* n1_b   = (const float*)d_in[p + 1];
    const float* sr_w   = (const float*)d_in[p + 2];
    const float* sr_b   = (const float*)d_in[p + 3];
    const float* an_g   = (const float*)d_in[p + 4];
    const float* an_b   = (const float*)d_in[p + 5];
    const float* qkv_w  = (const float*)d_in[p + 6];
    const float* proj_w = (const float*)d_in[p + 7];
    const float* proj_b = (const float*)d_in[p + 8];
    const float* n2_g   = (const float*)d_in[p + 9];
    const float* n2_b   = (const float*)d_in[p + 10];
    const float* fc1_w  = (const float*)d_in[p + 11];
    const float* fc1_b  = (const float*)d_in[p + 12];
    const float* dw_w   = (const float*)d_in[p + 13];
    const float* dw_b   = (const float*)d_in[p + 14];
    const float* fc2_w  = (const float*)d_in[p + 15];
    const float* fc2_b  = (const float*)d_in[p + 16];
    const float* ca_w1  = (const float*)d_in[p + 17];
    const float* ca_w2  = (const float*)d_in[p + 18];
    const float* sp_w   = (const float*)d_in[p + 19];
    const float* sp_b   = (const float*)d_in[p + 20];
    float* out = (float*)d_out;

    float *pxn, *pb1, *pb2;
    __nv_bfloat16 *pqkv16, *pa16, *ph16a, *ph16b, *pw16;
    cudaGetSymbolAddress((void**)&pxn,    g_xn);
    cudaGetSymbolAddress((void**)&pb1,    g_b1);
    cudaGetSymbolAddress((void**)&pb2,    g_b2);
    cudaGetSymbolAddress((void**)&pqkv16, g_qkv16);
    cudaGetSymbolAddress((void**)&pa16,   g_a16);
    cudaGetSymbolAddress((void**)&ph16a,  g_h16a);
    cudaGetSymbolAddress((void**)&ph16b,  g_h16b);
    cudaGetSymbolAddress((void**)&pw16,   g_w16);

    const int TPB = 256;
    const int GEMM_SMEM = NSTAGE * SSTG * 2;   // 98304 bytes
    cudaFuncSetAttribute(gemm_bf16<float>, cudaFuncAttributeMaxDynamicSharedMemorySize,
                         GEMM_SMEM);
    cudaFuncSetAttribute(gemm_bf16<__nv_bfloat16>, cudaFuncAttributeMaxDynamicSharedMemorySize,
                         GEMM_SMEM);

    // 0. bf16 weight conversion (one kernel)
    f2bf_all<<<(393216 + TPB - 1) / TPB, TPB>>>(qkv_w, proj_w, fc1_w, fc2_w, pw16);

    // 1. xn = LN1(x)
    ln256<float><<<ROWS_ * 32 / TPB, TPB>>>(x, pxn, n1_g, n1_b);
    // 2+3. xa16 = bf16(xn + gelu(LN_act(dwconv3(xn))))  (fused)
    sr_fuse<<<ROWS_, TPB>>>(pxn, pa16, sr_w, sr_b, an_g, an_b);
    // 4. qkv = xa @ qkv_w^T  (bf16 out)
    {
        dim3 g(3 * C_ / 128, ROWS_ / 128);
        gemm_bf16<__nv_bfloat16><<<g, TPB, GEMM_SMEM>>>(pa16, pw16 + W16_QKV, pqkv16,
                                                        ROWS_, 3 * C_, C_, nullptr, nullptr, nullptr);
    }
    // 5. q column-softmax stats
    {
        dim3 g(B_, 64);
        qsoft_part<<<g, TPB>>>(pqkv16);
        qsoft_comb<<<(B_ * C_ + TPB - 1) / TPB, TPB>>>();
    }
    // 6. ctx = softmax_d(k)^T v
    {
        dim3 g(16, HEADS_, B_);
        ctx_kernel<<<g, TPB>>>(pqkv16);
        ctx_comb<<<(B_ * HEADS_ * D_ * D_ + TPB - 1) / TPB, TPB>>>();
    }
    // 7. attn = softmax_N(q) @ ctx -> a16 (bf16)
    {
        dim3 g(N_ / 64, B_);
        attn2<<<g, TPB>>>(pqkv16, pa16);
    }
    // 8. x2 = x + attn @ proj_w^T + proj_b + xn -> b1
    {
        dim3 g(C_ / 128, ROWS_ / 128);
        gemm_bf16<float><<<g, TPB, GEMM_SMEM>>>(pa16, pw16 + W16_PROJ, pb1,
                                                ROWS_, C_, C_, proj_b, x, pxn);
    }
    // 9. ln2(x2) -> a16 (bf16)
    ln256<__nv_bfloat16><<<ROWS_ * 32 / TPB, TPB>>>(pb1, pa16, n2_g, n2_b);
    // 10. fc1 -> h16a (bf16)
    {
        dim3 g(HID_ / 128, ROWS_ / 128);
        gemm_bf16<__nv_bfloat16><<<g, TPB, GEMM_SMEM>>>(pa16, pw16 + W16_FC1, ph16a,
                                                        ROWS_, HID_, C_, fc1_b, nullptr, nullptr);
    }
    // 11. dwconv + gelu (bf16, sliding window) -> h16b
    {
        dim3 g(HID_ / 4 / 16, 64, B_);
        dwconv3_bf16_v2<<<g, TPB>>>(ph16a, ph16b, dw_w, dw_b);
    }
    // 12. x3 = x2 + gelu_dw @ fc2_w^T + fc2_b -> b2
    {
        dim3 g(C_ / 128, ROWS_ / 128);
        gemm_bf16<float><<<g, TPB, GEMM_SMEM>>>(ph16b, pw16 + W16_FC2, pb2,
                                                ROWS_, C_, HID_, fc2_b, pb1, nullptr);
    }
    // 13. channel pools
    {
        dim3 g(B_, 64);
        cpool_part<<<g, TPB>>>(pb2);
        cpool_comb<<<(B_ * C_ + TPB - 1) / TPB, TPB>>>();
    }
    // 14. channel attention MLP
    ca_mlp<<<B_, TPB>>>(ca_w1, ca_w2);
    // 15. spatial pools of x3*ca
    spool<<<ROWS_ * 32 / TPB, TPB>>>(pb2);
    // 16. 7x7 spatial conv -> sa
    conv7<<<(ROWS_ + TPB - 1) / TPB, TPB>>>(sp_w, sp_b);
    // 17. out = x3 * ca * sa
    final_scale<<<(ROWS_ * 64 + TPB - 1) / TPB, TPB>>>(pb2, out);
}